// round 11
// baseline (speedup 1.0000x reference)
#include <cuda_runtime.h>
#include <cuda.h>
#include <cuda_fp16.h>
#include <math.h>
#include <stdint.h>

#define BB 4
#define TT 2048
#define EE 1024
#define HH 16
#define DD 64
#define MROWS (BB * TT)   // 8192

// ---------------------------------------------------------------------------
// Scratch (__device__ globals; allocation-free rule) — fp16 operands
// ---------------------------------------------------------------------------
__device__ __half g_xh[(size_t)MROWS * EE];
__device__ __half g_wqkvh[(size_t)3 * EE * EE];
__device__ __half g_wouth[(size_t)EE * EE];
__device__ __half g_qh[(size_t)BB * HH * TT * DD];  // scaled Q [bh][t][d]
__device__ __half g_kh[(size_t)BB * HH * TT * DD];  // K [bh][t][d]
__device__ __half g_vth[(size_t)BB * HH * DD * TT]; // V^T [bh][d][t]
__device__ __half g_atth[(size_t)MROWS * EE];       // attention out

// ---------------------------------------------------------------------------
// Helpers
// ---------------------------------------------------------------------------
__device__ __forceinline__ float ex2f(float x) {
    float y;
    asm("ex2.approx.f32 %0, %1;" : "=f"(y) : "f"(x));
    return y;
}

__device__ __forceinline__ uint32_t f2h2(float lo, float hi) {
    __half2 h = __floats2half2_rn(lo, hi);
    return *(uint32_t*)&h;
}

__device__ __forceinline__ void mma_f16(float c[4],
                                        uint32_t a0, uint32_t a1, uint32_t a2, uint32_t a3,
                                        uint32_t b0, uint32_t b1) {
    asm volatile(
        "mma.sync.aligned.m16n8k16.row.col.f32.f16.f16.f32 "
        "{%0,%1,%2,%3}, {%4,%5,%6,%7}, {%8,%9}, {%0,%1,%2,%3};\n"
        : "+f"(c[0]), "+f"(c[1]), "+f"(c[2]), "+f"(c[3])
        : "r"(a0), "r"(a1), "r"(a2), "r"(a3), "r"(b0), "r"(b1));
}

__device__ __forceinline__ void ldsm_x4(uint32_t& d0, uint32_t& d1, uint32_t& d2, uint32_t& d3,
                                        uint32_t addr) {
    asm volatile("ldmatrix.sync.aligned.m8n8.x4.shared.b16 {%0,%1,%2,%3}, [%4];"
                 : "=r"(d0), "=r"(d1), "=r"(d2), "=r"(d3) : "r"(addr));
}

__device__ __forceinline__ uint32_t smem_u32(const void* p) {
    uint32_t a;
    asm("{ .reg .u64 t; cvta.to.shared.u64 t, %1; cvt.u32.u64 %0, t; }"
        : "=r"(a) : "l"(p));
    return a;
}

#define MBARRIER_INIT(addr, cnt) \
    asm volatile("mbarrier.init.shared.b64 [%0], %1;" :: "r"((uint32_t)(addr)), "r"((uint32_t)(cnt)) : "memory")

#define MBARRIER_ARRIVE(addr) \
    asm volatile("mbarrier.arrive.shared.b64 _, [%0];" :: "r"((uint32_t)(addr)) : "memory")

#define MBARRIER_EXPECT_TX(addr, bytes) \
    asm volatile("mbarrier.arrive.expect_tx.shared.b64 _, [%0], %1;" :: "r"((uint32_t)(addr)), "r"((uint32_t)(bytes)) : "memory")

#define MBARRIER_WAIT_PARITY(addr, parity) do {                                   \
    uint32_t _mb = (uint32_t)(addr);                                              \
    uint32_t _ph = (uint32_t)(parity);                                            \
    uint32_t _done;                                                               \
    asm volatile("{\n\t.reg .pred p;\n\t"                                         \
        "mbarrier.try_wait.parity.acquire.cta.shared::cta.b64 p, [%1], %2;\n\t"   \
        "selp.b32 %0, 1, 0, p;\n\t}"                                              \
        : "=r"(_done) : "r"(_mb), "r"(_ph) : "memory");                           \
    if (!_done) {                                                                 \
        asm volatile("{\n\t.reg .pred P1;\n\t"                                    \
            "WAIT_LOOP_%=:\n\t"                                                   \
            "mbarrier.try_wait.parity.acquire.cta.shared::cta.b64 P1, [%0], %1, 0x989680;\n\t" \
            "@P1 bra.uni WAIT_DONE_%=;\n\t"                                       \
            "bra.uni WAIT_LOOP_%=;\n\t"                                           \
            "WAIT_DONE_%=:\n\t}"                                                  \
            :: "r"(_mb), "r"(_ph) : "memory");                                    \
    }                                                                             \
} while (0)

#define TMA_LOAD_2D(smem_addr, map_ptr, cx, cy, mbar) \
    asm volatile("cp.async.bulk.tensor.2d.shared::cta.global.tile.mbarrier::complete_tx::bytes " \
                 "[%0], [%1, {%2, %3}], [%4];" \
                 :: "r"((uint32_t)(smem_addr)), "l"(map_ptr), \
                    "r"((int32_t)(cx)), "r"((int32_t)(cy)), "r"((uint32_t)(mbar)) : "memory")

// Q pre-scale: D^-0.5 * log2(e)
#define QSCALE 0.18033688011112042f

// ---------------------------------------------------------------------------
// Prep: f32 -> fp16
// ---------------------------------------------------------------------------
__global__ void conv_half(const float4* __restrict__ src, uint2* __restrict__ dst, int n4)
{
    int i = blockIdx.x * blockDim.x + threadIdx.x;
    if (i >= n4) return;
    float4 v = src[i];
    dst[i] = make_uint2(f2h2(v.x, v.y), f2h2(v.z, v.w));
}

// ---------------------------------------------------------------------------
// fp16 GEMM (NT): unchanged from R10 (proven 119.6us / 71% tensor).
// CTA 128x128, BK=64, 16 chunks, 8 warps (2m x 4n), warp tile 64x32.
// 3-stage TMA full/empty pipeline, no block syncs in mainloop, 2 CTAs/SM.
// ---------------------------------------------------------------------------
#define G_NCH 16
#define G_STAGE_BYTES 32768           // A 128x128B + B 128x128B
#define GEMM_SMEM_BYTES (1024 + 3 * G_STAGE_BYTES)

template <int MODE>
__global__ __launch_bounds__(256, 2)
void gemm_tma(const __grid_constant__ CUtensorMap tmA,
              const __grid_constant__ CUtensorMap tmB,
              float* __restrict__ C)
{
    extern __shared__ char smraw[];
    uint32_t sb = smem_u32(smraw);
    sb = (sb + 1023u) & ~1023u;

    const int tid = threadIdx.x, lane = tid & 31, wid = tid >> 5;
    const int wm = wid & 1, wn = wid >> 1;
    const int g = lane >> 2, t = lane & 3;
    const int m0 = blockIdx.y * 128;
    const int n0 = blockIdx.x * 128;

    const uint32_t mbf = sb;             // full  @ +0,8,16
    const uint32_t mbe = sb + 24;        // empty @ +24,32,40
    const uint32_t st0 = sb + 1024;

    if (tid == 0) {
#pragma unroll
        for (int s = 0; s < 3; ++s) {
            MBARRIER_INIT(mbf + s * 8, 1);
            MBARRIER_INIT(mbe + s * 8, 8);
        }
    }
    __syncthreads();

    auto produce = [&](int c) {
        const int s = c % 3;
        MBARRIER_EXPECT_TX(mbf + s * 8, G_STAGE_BYTES);
        const uint32_t sa = st0 + s * G_STAGE_BYTES;
        TMA_LOAD_2D(sa,         &tmA, c * 64, m0, mbf + s * 8);
        TMA_LOAD_2D(sa + 16384, &tmB, c * 64, n0, mbf + s * 8);
    };

    if (tid == 0) { produce(0); produce(1); produce(2); }

    float acc[4][4][4];
#pragma unroll
    for (int mt = 0; mt < 4; ++mt)
#pragma unroll
        for (int nt = 0; nt < 4; ++nt)
#pragma unroll
            for (int j = 0; j < 4; ++j) acc[mt][nt][j] = 0.f;

    for (int c = 0; c < G_NCH; ++c) {
        MBARRIER_WAIT_PARITY(mbf + (c % 3) * 8, (c / 3) & 1);

        const uint32_t sa = st0 + (c % 3) * G_STAGE_BYTES;
        const uint32_t sw = sa + 16384;

        uint32_t af[2][4][4], bf[2][4][2];
        auto ldfrag = [&](int ks, int p) {
            const int kc2 = ks * 2;
#pragma unroll
            for (int mt = 0; mt < 4; ++mt) {
                const int r = wm * 64 + mt * 16 + (lane & 7) + ((lane >> 3) & 1) * 8;
                const int cc = kc2 + (lane >> 4);
                ldsm_x4(af[p][mt][0], af[p][mt][1], af[p][mt][2], af[p][mt][3],
                        sa + r * 128 + ((cc ^ (r & 7)) << 4));
            }
#pragma unroll
            for (int j = 0; j < 2; ++j) {
                const int r = wn * 32 + (j * 2 + ((lane >> 4) & 1)) * 8 + (lane & 7);
                const int cc = kc2 + ((lane >> 3) & 1);
                uint32_t d0, d1, d2, d3;
                ldsm_x4(d0, d1, d2, d3, sw + r * 128 + ((cc ^ (r & 7)) << 4));
                bf[p][2 * j][0] = d0; bf[p][2 * j][1] = d1;
                bf[p][2 * j + 1][0] = d2; bf[p][2 * j + 1][1] = d3;
            }
        };

        ldfrag(0, 0);
#pragma unroll
        for (int ks = 0; ks < 4; ++ks) {
            if (ks < 3) {
                ldfrag(ks + 1, (ks + 1) & 1);
                if (ks == 2 && lane == 0)
                    MBARRIER_ARRIVE(mbe + (c % 3) * 8);
            }
            const int p = ks & 1;
#pragma unroll
            for (int mt = 0; mt < 4; ++mt)
#pragma unroll
                for (int nt = 0; nt < 4; ++nt)
                    mma_f16(acc[mt][nt], af[p][mt][0], af[p][mt][1], af[p][mt][2], af[p][mt][3],
                            bf[p][nt][0], bf[p][nt][1]);
        }

        if (tid == 0 && c + 3 < G_NCH) {
            MBARRIER_WAIT_PARITY(mbe + (c % 3) * 8, (c / 3) & 1);
            produce(c + 3);
        }
    }

    // Epilogue
#pragma unroll
    for (int mt = 0; mt < 4; ++mt) {
#pragma unroll
        for (int nt = 0; nt < 4; ++nt) {
            const int r0 = m0 + wm * 64 + mt * 16 + g;
            const int col = n0 + wn * 32 + nt * 8 + 2 * t;
            if (MODE == 0) {
                *(float2*)(C + (size_t)r0 * EE + col) =
                    make_float2(acc[mt][nt][0], acc[mt][nt][1]);
                *(float2*)(C + (size_t)(r0 + 8) * EE + col) =
                    make_float2(acc[mt][nt][2], acc[mt][nt][3]);
            } else {
                const int which = col >> 10;
                const int rem = col & 1023;
                const int h = rem >> 6;
                const int d = rem & 63;
#pragma unroll
                for (int half = 0; half < 2; ++half) {
                    const int row = r0 + half * 8;
                    const float v0 = acc[mt][nt][2 * half];
                    const float v1 = acc[mt][nt][2 * half + 1];
                    const int bh = (row >> 11) * HH + h;
                    const int tt = row & 2047;
                    if (which == 0) {
                        *(uint32_t*)(g_qh + ((size_t)bh * TT + tt) * DD + d) =
                            f2h2(v0 * QSCALE, v1 * QSCALE);
                    } else if (which == 1) {
                        *(uint32_t*)(g_kh + ((size_t)bh * TT + tt) * DD + d) =
                            f2h2(v0, v1);
                    } else {
                        g_vth[((size_t)bh * DD + d) * TT + tt]     = __float2half(v0);
                        g_vth[((size_t)bh * DD + d + 1) * TT + tt] = __float2half(v1);
                    }
                }
            }
        }
    }
}

// ---------------------------------------------------------------------------
// Causal flash attention (fp16 mma, fp32 accum): q-tile 128, kv-tile 64,
// 4 warps x 32 q-rows each (2 m-frags), 3 CTAs/SM (launch_bounds(128,3)).
// K/VT B-fragments shared across both m-frags -> 35% less LDS per mma.
// P via SMEM (R8-proven bit-exact path). TMA SW128, 2-stage kv pipeline,
// no block syncs in mainloop. Softmax in log2 domain (ex2).
// SMEM (from aligned base):
//   0      : barriers (q_full @0, kv_full @8,16, kv_empty @24,32)
//   1024   : Q   (128 x 128B = 16KB)
//   17408  : P   (128 x 128B = 16KB)
//   33792  : K/VT stages (2 x 16KB: K 8KB + VT 8KB each)
// ---------------------------------------------------------------------------
#define FA_Q_OFF   1024
#define FA_P_OFF   (FA_Q_OFF + 16384)
#define FA_KV_OFF  (FA_P_OFF + 16384)
#define FA_SMEM_BYTES (FA_KV_OFF + 2 * 16384 + 1024)

__global__ __launch_bounds__(128, 3)
void flash_attn_tma(const __grid_constant__ CUtensorMap tmQ,
                    const __grid_constant__ CUtensorMap tmK,
                    const __grid_constant__ CUtensorMap tmVT)
{
    extern __shared__ char smraw[];
    uint32_t sb = smem_u32(smraw);
    sb = (sb + 1023u) & ~1023u;

    const int qt = gridDim.x - 1 - blockIdx.x;   // long tiles first
    const int bh = blockIdx.y;
    const int q0 = qt * 128;

    const int tid = threadIdx.x, lane = tid & 31, wid = tid >> 5;
    const int g = lane >> 2, t = lane & 3;
    const int wrow = wid * 32;                   // warp owns 32 q-rows

    const uint32_t qb  = sb + FA_Q_OFF;
    const uint32_t pb  = sb + FA_P_OFF;
    const uint32_t kvb = sb + FA_KV_OFF;
    const uint32_t mbf = sb + 8;    // kv full @ 8,16
    const uint32_t mbe = sb + 24;   // kv empty @ 24,32

    if (tid == 0) {
        MBARRIER_INIT(sb + 0, 1);
#pragma unroll
        for (int s = 0; s < 2; ++s) {
            MBARRIER_INIT(mbf + s * 8, 1);
            MBARRIER_INIT(mbe + s * 8, 4);       // 4 warps
        }
    }
    __syncthreads();

    auto produce_kv = [&](int kt) {
        const int s = kt & 1;
        const int k0 = kt * 64;
        MBARRIER_EXPECT_TX(mbf + s * 8, 16384);
        TMA_LOAD_2D(kvb + s * 16384,        &tmK,  0,  bh * TT + k0, mbf + s * 8);
        TMA_LOAD_2D(kvb + s * 16384 + 8192, &tmVT, k0, bh * 64,      mbf + s * 8);
    };

    const int ktmax = 2 * qt + 1;
    if (tid == 0) {
        MBARRIER_EXPECT_TX(sb + 0, 16384);
        TMA_LOAD_2D(qb, &tmQ, 0, bh * TT + q0, sb + 0);
        produce_kv(0);
        produce_kv(1);
    }
    MBARRIER_WAIT_PARITY(sb + 0, 0);

    float o[2][8][4];
#pragma unroll
    for (int mt = 0; mt < 2; ++mt)
#pragma unroll
        for (int nt = 0; nt < 8; ++nt)
#pragma unroll
            for (int j = 0; j < 4; ++j) o[mt][nt][j] = 0.f;
    float mr[2][2] = {{-INFINITY, -INFINITY}, {-INFINITY, -INFINITY}};
    float lr[2][2] = {{0.f, 0.f}, {0.f, 0.f}};

    for (int kt = 0; kt <= ktmax; ++kt) {
        const int s2 = kt & 1;
        const int ph = (kt >> 1) & 1;
        MBARRIER_WAIT_PARITY(mbf + s2 * 8, ph);

        const int k0 = kt * 64;
        const bool active = (k0 <= q0 + wrow + 31);

        if (active) {
            const uint32_t ks_b = kvb + s2 * 16384;
            const uint32_t vt_b = ks_b + 8192;

            // --- S = Q K^T (B fragments of K shared across both m-frags) ---
            float s[2][8][4];
#pragma unroll
            for (int mt = 0; mt < 2; ++mt)
#pragma unroll
                for (int nt = 0; nt < 8; ++nt)
#pragma unroll
                    for (int j = 0; j < 4; ++j) s[mt][nt][j] = 0.f;

#pragma unroll
            for (int ks = 0; ks < 4; ++ks) {
                const int kc2 = ks * 2;
                uint32_t a[2][4];
#pragma unroll
                for (int mt = 0; mt < 2; ++mt) {
                    const int r = wrow + mt * 16 + (lane & 7) + ((lane >> 3) & 1) * 8;
                    const int cc = kc2 + (lane >> 4);
                    ldsm_x4(a[mt][0], a[mt][1], a[mt][2], a[mt][3],
                            qb + r * 128 + ((cc ^ (r & 7)) << 4));
                }
                uint32_t b[8][2];
#pragma unroll
                for (int j = 0; j < 4; ++j) {
                    const int r = (j * 2 + ((lane >> 4) & 1)) * 8 + (lane & 7);
                    const int cc = kc2 + ((lane >> 3) & 1);
                    uint32_t d0, d1, d2, d3;
                    ldsm_x4(d0, d1, d2, d3, ks_b + r * 128 + ((cc ^ (r & 7)) << 4));
                    b[2 * j][0] = d0; b[2 * j][1] = d1;
                    b[2 * j + 1][0] = d2; b[2 * j + 1][1] = d3;
                }
#pragma unroll
                for (int mt = 0; mt < 2; ++mt)
#pragma unroll
                    for (int nt = 0; nt < 8; ++nt)
                        mma_f16(s[mt][nt], a[mt][0], a[mt][1], a[mt][2], a[mt][3],
                                b[nt][0], b[nt][1]);
            }

            // --- causal mask (diagonal region only) ---
            if (k0 + 63 > q0 + wrow) {
#pragma unroll
                for (int mt = 0; mt < 2; ++mt) {
                    const int rlo = q0 + wrow + mt * 16 + g;
#pragma unroll
                    for (int nt = 0; nt < 8; ++nt) {
                        const int key = k0 + nt * 8 + 2 * t;
                        if (key > rlo)         s[mt][nt][0] = -INFINITY;
                        if (key + 1 > rlo)     s[mt][nt][1] = -INFINITY;
                        if (key > rlo + 8)     s[mt][nt][2] = -INFINITY;
                        if (key + 1 > rlo + 8) s[mt][nt][3] = -INFINITY;
                    }
                }
            }

            // --- online softmax (log2 domain) + P store (fp16, swizzled) ---
#pragma unroll
            for (int mt = 0; mt < 2; ++mt) {
                float mx0 = -INFINITY, mx1 = -INFINITY;
#pragma unroll
                for (int nt = 0; nt < 8; ++nt) {
                    mx0 = fmaxf(mx0, fmaxf(s[mt][nt][0], s[mt][nt][1]));
                    mx1 = fmaxf(mx1, fmaxf(s[mt][nt][2], s[mt][nt][3]));
                }
                mx0 = fmaxf(mx0, __shfl_xor_sync(0xffffffffu, mx0, 1));
                mx0 = fmaxf(mx0, __shfl_xor_sync(0xffffffffu, mx0, 2));
                mx1 = fmaxf(mx1, __shfl_xor_sync(0xffffffffu, mx1, 1));
                mx1 = fmaxf(mx1, __shfl_xor_sync(0xffffffffu, mx1, 2));

                const float mn0 = fmaxf(mr[mt][0], mx0);
                const float mn1 = fmaxf(mr[mt][1], mx1);
                const float al0 = ex2f(mr[mt][0] - mn0);
                const float al1 = ex2f(mr[mt][1] - mn1);
                mr[mt][0] = mn0; mr[mt][1] = mn1;

                float s0 = 0.f, s1 = 0.f;
#pragma unroll
                for (int nt = 0; nt < 8; ++nt) {
                    s[mt][nt][0] = ex2f(s[mt][nt][0] - mn0);
                    s[mt][nt][1] = ex2f(s[mt][nt][1] - mn0);
                    s[mt][nt][2] = ex2f(s[mt][nt][2] - mn1);
                    s[mt][nt][3] = ex2f(s[mt][nt][3] - mn1);
                    s0 += s[mt][nt][0] + s[mt][nt][1];
                    s1 += s[mt][nt][2] + s[mt][nt][3];
                }
                s0 += __shfl_xor_sync(0xffffffffu, s0, 1);
                s0 += __shfl_xor_sync(0xffffffffu, s0, 2);
                s1 += __shfl_xor_sync(0xffffffffu, s1, 1);
                s1 += __shfl_xor_sync(0xffffffffu, s1, 2);

                lr[mt][0] = lr[mt][0] * al0 + s0;
                lr[mt][1] = lr[mt][1] * al1 + s1;
#pragma unroll
                for (int nt = 0; nt < 8; ++nt) {
                    o[mt][nt][0] *= al0; o[mt][nt][1] *= al0;
                    o[mt][nt][2] *= al1; o[mt][nt][3] *= al1;
                }

#pragma unroll
                for (int half = 0; half < 2; ++half) {
                    const int pr = wrow + mt * 16 + g + half * 8;
#pragma unroll
                    for (int nt = 0; nt < 8; ++nt) {
                        const uint32_t addr = pb + pr * 128 +
                                              ((nt ^ (pr & 7)) << 4) + 4 * t;
                        const uint32_t val = f2h2(s[mt][nt][2 * half],
                                                  s[mt][nt][2 * half + 1]);
                        asm volatile("st.shared.b32 [%0], %1;"
                                     :: "r"(addr), "r"(val) : "memory");
                    }
                }
            }
            __syncwarp();

            // --- O += P V (VT B-fragments shared across both m-frags) ---
#pragma unroll
            for (int ks = 0; ks < 4; ++ks) {
                const int kc2 = ks * 2;
                uint32_t a[2][4];
#pragma unroll
                for (int mt = 0; mt < 2; ++mt) {
                    const int r = wrow + mt * 16 + (lane & 7) + ((lane >> 3) & 1) * 8;
                    const int cc = kc2 + (lane >> 4);
                    ldsm_x4(a[mt][0], a[mt][1], a[mt][2], a[mt][3],
                            pb + r * 128 + ((cc ^ (r & 7)) << 4));
                }
                uint32_t b[8][2];
#pragma unroll
                for (int j = 0; j < 4; ++j) {
                    const int r = (j * 2 + ((lane >> 4) & 1)) * 8 + (lane & 7);
                    const int cc = kc2 + ((lane >> 3) & 1);
                    uint32_t d0, d1, d2, d3;
                    ldsm_x4(d0, d1, d2, d3, vt_b + r * 128 + ((cc ^ (r & 7)) << 4));
                    b[2 * j][0] = d0; b[2 * j][1] = d1;
                    b[2 * j + 1][0] = d2; b[2 * j + 1][1] = d3;
                }
#pragma unroll
                for (int mt = 0; mt < 2; ++mt)
#pragma unroll
                    for (int nt = 0; nt < 8; ++nt)
                        mma_f16(o[mt][nt], a[mt][0], a[mt][1], a[mt][2], a[mt][3],
                                b[nt][0], b[nt][1]);
            }
        }

        if (lane == 0) MBARRIER_ARRIVE(mbe + s2 * 8);

        if (tid == 0 && kt + 2 <= ktmax) {
            MBARRIER_WAIT_PARITY(mbe + s2 * 8, ph);
            produce_kv(kt + 2);
        }
    }

    // --- epilogue: normalize, write fp16 att [B,T,E] ---
    const int b = bh >> 4, h = bh & 15;
#pragma unroll
    for (int mt = 0; mt < 2; ++mt) {
#pragma unroll
        for (int half = 0; half < 2; ++half) {
            const int row = q0 + wrow + mt * 16 + g + half * 8;
            const float inv = 1.0f / lr[mt][half];
#pragma unroll
            for (int nt = 0; nt < 8; ++nt) {
                const int col = h * 64 + nt * 8 + 2 * t;
                *(uint32_t*)(g_atth + ((size_t)b * TT + row) * EE + col) =
                    f2h2(o[mt][nt][2 * half] * inv, o[mt][nt][2 * half + 1] * inv);
            }
        }
    }
}

// ---------------------------------------------------------------------------
// Host
// ---------------------------------------------------------------------------
typedef CUresult (*EncodeFn)(CUtensorMap*, CUtensorMapDataType, cuuint32_t, void*,
                             const cuuint64_t*, const cuuint64_t*, const cuuint32_t*,
                             const cuuint32_t*, CUtensorMapInterleave, CUtensorMapSwizzle,
                             CUtensorMapL2promotion, CUtensorMapFloatOOBfill);

static void make_tm(EncodeFn enc, CUtensorMap* tm, void* ptr,
                    uint64_t d0, uint64_t d1, uint32_t b0, uint32_t b1)
{
    cuuint64_t dims[2]    = {d0, d1};
    cuuint64_t strides[1] = {d0 * 2};
    cuuint32_t box[2]     = {b0, b1};
    cuuint32_t estr[2]    = {1, 1};
    enc(tm, CU_TENSOR_MAP_DATA_TYPE_FLOAT16, 2, ptr, dims, strides, box, estr,
        CU_TENSOR_MAP_INTERLEAVE_NONE, CU_TENSOR_MAP_SWIZZLE_128B,
        CU_TENSOR_MAP_L2_PROMOTION_L2_128B, CU_TENSOR_MAP_FLOAT_OOB_FILL_NONE);
}

extern "C" void kernel_launch(void* const* d_in, const int* in_sizes, int n_in,
                              void* d_out, int out_size)
{
    const float* x    = (const float*)d_in[0];   // [B,T,E]
    const float* Wqkv = (const float*)d_in[1];   // [3E,E]
    const float* Wout = (const float*)d_in[2];   // [E,E]
    float* out = (float*)d_out;                  // [B,T,E]

    void *xh, *wqkvh, *wouth, *atth, *qp, *kp, *vtp;
    cudaGetSymbolAddress(&xh, g_xh);
    cudaGetSymbolAddress(&wqkvh, g_wqkvh);
    cudaGetSymbolAddress(&wouth, g_wouth);
    cudaGetSymbolAddress(&atth, g_atth);
    cudaGetSymbolAddress(&qp, g_qh);
    cudaGetSymbolAddress(&kp, g_kh);
    cudaGetSymbolAddress(&vtp, g_vth);

    void* pf = nullptr;
    cudaDriverEntryPointQueryResult qr;
    cudaGetDriverEntryPoint("cuTensorMapEncodeTiled", &pf, cudaEnableDefault, &qr);
    EncodeFn enc = (EncodeFn)pf;

    CUtensorMap tmX, tmWqkv, tmAtt, tmWout, tmQ, tmK, tmVT;
    make_tm(enc, &tmX,    xh,    1024, MROWS,               64, 128);
    make_tm(enc, &tmWqkv, wqkvh, 1024, 3072,                64, 128);
    make_tm(enc, &tmAtt,  atth,  1024, MROWS,               64, 128);
    make_tm(enc, &tmWout, wouth, 1024, 1024,                64, 128);
    make_tm(enc, &tmQ,    qp,    64,   (uint64_t)BB * HH * TT, 64, 128);
    make_tm(enc, &tmK,    kp,    64,   (uint64_t)BB * HH * TT, 64, 64);
    make_tm(enc, &tmVT,   vtp,   2048, (uint64_t)BB * HH * DD, 64, 64);

    cudaFuncSetAttribute(gemm_tma<0>, cudaFuncAttributeMaxDynamicSharedMemorySize, GEMM_SMEM_BYTES);
    cudaFuncSetAttribute(gemm_tma<1>, cudaFuncAttributeMaxDynamicSharedMemorySize, GEMM_SMEM_BYTES);
    cudaFuncSetAttribute(flash_attn_tma, cudaFuncAttributeMaxDynamicSharedMemorySize, FA_SMEM_BYTES);

    // 0) convert operands to fp16
    {
        int n4 = MROWS * EE / 4;
        conv_half<<<(n4 + 255) / 256, 256>>>((const float4*)x, (uint2*)xh, n4);
        n4 = 3 * EE * EE / 4;
        conv_half<<<(n4 + 255) / 256, 256>>>((const float4*)Wqkv, (uint2*)wqkvh, n4);
        n4 = EE * EE / 4;
        conv_half<<<(n4 + 255) / 256, 256>>>((const float4*)Wout, (uint2*)wouth, n4);
    }

    // 1) QKV projection + scatter (q scaled, v transposed)
    {
        dim3 grid(3 * EE / 128, MROWS / 128);   // (24, 64)
        gemm_tma<1><<<grid, 256, GEMM_SMEM_BYTES>>>(tmX, tmWqkv, nullptr);
    }

    // 2) Causal flash attention -> g_atth (fp16)
    {
        dim3 grid(TT / 128, BB * HH);           // (16, 64)
        flash_attn_tma<<<grid, 128, FA_SMEM_BYTES>>>(tmQ, tmK, tmVT);
    }

    // 3) Output projection (fp32 out)
    {
        dim3 grid(EE / 128, MROWS / 128);       // (8, 64)
        gemm_tma<0><<<grid, 256, GEMM_SMEM_BYTES>>>(tmAtt, tmWout, out);
    }
}

// round 13
// speedup vs baseline: 1.1196x; 1.1196x over previous
#include <cuda_runtime.h>
#include <cuda.h>
#include <cuda_fp16.h>
#include <math.h>
#include <stdint.h>

#define BB 4
#define TT 2048
#define EE 1024
#define HH 16
#define DD 64
#define MROWS (BB * TT)   // 8192

// ---------------------------------------------------------------------------
// Scratch (__device__ globals; allocation-free rule) — fp16 operands
// ---------------------------------------------------------------------------
__device__ __half g_xh[(size_t)MROWS * EE];
__device__ __half g_wqkvh[(size_t)3 * EE * EE];
__device__ __half g_wouth[(size_t)EE * EE];
__device__ __half g_qh[(size_t)BB * HH * TT * DD];  // scaled Q [bh][t][d]
__device__ __half g_kh[(size_t)BB * HH * TT * DD];  // K [bh][t][d]
__device__ __half g_vth[(size_t)BB * HH * DD * TT]; // V^T [bh][d][t]
__device__ __half g_atth[(size_t)MROWS * EE];       // attention out

// ---------------------------------------------------------------------------
// Helpers
// ---------------------------------------------------------------------------
__device__ __forceinline__ float ex2f(float x) {
    float y;
    asm("ex2.approx.f32 %0, %1;" : "=f"(y) : "f"(x));
    return y;
}

__device__ __forceinline__ uint32_t f2h2(float lo, float hi) {
    __half2 h = __floats2half2_rn(lo, hi);
    return *(uint32_t*)&h;
}

__device__ __forceinline__ void mma_f16(float c[4],
                                        uint32_t a0, uint32_t a1, uint32_t a2, uint32_t a3,
                                        uint32_t b0, uint32_t b1) {
    asm volatile(
        "mma.sync.aligned.m16n8k16.row.col.f32.f16.f16.f32 "
        "{%0,%1,%2,%3}, {%4,%5,%6,%7}, {%8,%9}, {%0,%1,%2,%3};\n"
        : "+f"(c[0]), "+f"(c[1]), "+f"(c[2]), "+f"(c[3])
        : "r"(a0), "r"(a1), "r"(a2), "r"(a3), "r"(b0), "r"(b1));
}

__device__ __forceinline__ void ldsm_x4(uint32_t& d0, uint32_t& d1, uint32_t& d2, uint32_t& d3,
                                        uint32_t addr) {
    asm volatile("ldmatrix.sync.aligned.m8n8.x4.shared.b16 {%0,%1,%2,%3}, [%4];"
                 : "=r"(d0), "=r"(d1), "=r"(d2), "=r"(d3) : "r"(addr));
}

__device__ __forceinline__ uint32_t smem_u32(const void* p) {
    uint32_t a;
    asm("{ .reg .u64 t; cvta.to.shared.u64 t, %1; cvt.u32.u64 %0, t; }"
        : "=r"(a) : "l"(p));
    return a;
}

#define MBARRIER_INIT(addr, cnt) \
    asm volatile("mbarrier.init.shared.b64 [%0], %1;" :: "r"((uint32_t)(addr)), "r"((uint32_t)(cnt)) : "memory")

#define MBARRIER_ARRIVE(addr) \
    asm volatile("mbarrier.arrive.shared.b64 _, [%0];" :: "r"((uint32_t)(addr)) : "memory")

#define MBARRIER_EXPECT_TX(addr, bytes) \
    asm volatile("mbarrier.arrive.expect_tx.shared.b64 _, [%0], %1;" :: "r"((uint32_t)(addr)), "r"((uint32_t)(bytes)) : "memory")

#define MBARRIER_WAIT_PARITY(addr, parity) do {                                   \
    uint32_t _mb = (uint32_t)(addr);                                              \
    uint32_t _ph = (uint32_t)(parity);                                            \
    uint32_t _done;                                                               \
    asm volatile("{\n\t.reg .pred p;\n\t"                                         \
        "mbarrier.try_wait.parity.acquire.cta.shared::cta.b64 p, [%1], %2;\n\t"   \
        "selp.b32 %0, 1, 0, p;\n\t}"                                              \
        : "=r"(_done) : "r"(_mb), "r"(_ph) : "memory");                           \
    if (!_done) {                                                                 \
        asm volatile("{\n\t.reg .pred P1;\n\t"                                    \
            "WAIT_LOOP_%=:\n\t"                                                   \
            "mbarrier.try_wait.parity.acquire.cta.shared::cta.b64 P1, [%0], %1, 0x989680;\n\t" \
            "@P1 bra.uni WAIT_DONE_%=;\n\t"                                       \
            "bra.uni WAIT_LOOP_%=;\n\t"                                           \
            "WAIT_DONE_%=:\n\t}"                                                  \
            :: "r"(_mb), "r"(_ph) : "memory");                                    \
    }                                                                             \
} while (0)

#define TMA_LOAD_2D(smem_addr, map_ptr, cx, cy, mbar) \
    asm volatile("cp.async.bulk.tensor.2d.shared::cta.global.tile.mbarrier::complete_tx::bytes " \
                 "[%0], [%1, {%2, %3}], [%4];" \
                 :: "r"((uint32_t)(smem_addr)), "l"(map_ptr), \
                    "r"((int32_t)(cx)), "r"((int32_t)(cy)), "r"((uint32_t)(mbar)) : "memory")

// Q pre-scale: D^-0.5 * log2(e)
#define QSCALE 0.18033688011112042f

// ---------------------------------------------------------------------------
// Prep: f32 -> fp16
// ---------------------------------------------------------------------------
__global__ void conv_half(const float4* __restrict__ src, uint2* __restrict__ dst, int n4)
{
    int i = blockIdx.x * blockDim.x + threadIdx.x;
    if (i >= n4) return;
    float4 v = src[i];
    dst[i] = make_uint2(f2h2(v.x, v.y), f2h2(v.z, v.w));
}

// ---------------------------------------------------------------------------
// fp16 GEMM (NT): CTA 128x128, BK=64, 16 chunks, 8 warps (2m x 4n),
// warp tile 64x32. 3-stage TMA full/empty pipeline, no block syncs in
// mainloop, 2 CTAs/SM.
// MODE 0: fp32 row-major store. MODE 1: QKV scatter (q scaled, v transposed).
// ---------------------------------------------------------------------------
#define G_NCH 16
#define G_STAGE_BYTES 32768           // A 128x128B + B 128x128B
#define GEMM_SMEM_BYTES (1024 + 3 * G_STAGE_BYTES)

template <int MODE>
__global__ __launch_bounds__(256, 2)
void gemm_tma(const __grid_constant__ CUtensorMap tmA,
              const __grid_constant__ CUtensorMap tmB,
              float* __restrict__ C)
{
    extern __shared__ char smraw[];
    uint32_t sb = smem_u32(smraw);
    sb = (sb + 1023u) & ~1023u;

    const int tid = threadIdx.x, lane = tid & 31, wid = tid >> 5;
    const int wm = wid & 1, wn = wid >> 1;
    const int g = lane >> 2, t = lane & 3;
    const int m0 = blockIdx.y * 128;
    const int n0 = blockIdx.x * 128;

    const uint32_t mbf = sb;             // full  @ +0,8,16
    const uint32_t mbe = sb + 24;        // empty @ +24,32,40
    const uint32_t st0 = sb + 1024;

    if (tid == 0) {
#pragma unroll
        for (int s = 0; s < 3; ++s) {
            MBARRIER_INIT(mbf + s * 8, 1);
            MBARRIER_INIT(mbe + s * 8, 8);
        }
    }
    __syncthreads();

    auto produce = [&](int c) {
        const int s = c % 3;
        MBARRIER_EXPECT_TX(mbf + s * 8, G_STAGE_BYTES);
        const uint32_t sa = st0 + s * G_STAGE_BYTES;
        TMA_LOAD_2D(sa,         &tmA, c * 64, m0, mbf + s * 8);
        TMA_LOAD_2D(sa + 16384, &tmB, c * 64, n0, mbf + s * 8);
    };

    if (tid == 0) { produce(0); produce(1); produce(2); }

    float acc[4][4][4];
#pragma unroll
    for (int mt = 0; mt < 4; ++mt)
#pragma unroll
        for (int nt = 0; nt < 4; ++nt)
#pragma unroll
            for (int j = 0; j < 4; ++j) acc[mt][nt][j] = 0.f;

    for (int c = 0; c < G_NCH; ++c) {
        MBARRIER_WAIT_PARITY(mbf + (c % 3) * 8, (c / 3) & 1);

        const uint32_t sa = st0 + (c % 3) * G_STAGE_BYTES;
        const uint32_t sw = sa + 16384;

        uint32_t af[2][4][4], bf[2][4][2];
        auto ldfrag = [&](int ks, int p) {
            const int kc2 = ks * 2;
#pragma unroll
            for (int mt = 0; mt < 4; ++mt) {
                const int r = wm * 64 + mt * 16 + (lane & 7) + ((lane >> 3) & 1) * 8;
                const int cc = kc2 + (lane >> 4);
                ldsm_x4(af[p][mt][0], af[p][mt][1], af[p][mt][2], af[p][mt][3],
                        sa + r * 128 + ((cc ^ (r & 7)) << 4));
            }
#pragma unroll
            for (int j = 0; j < 2; ++j) {
                const int r = wn * 32 + (j * 2 + ((lane >> 4) & 1)) * 8 + (lane & 7);
                const int cc = kc2 + ((lane >> 3) & 1);
                uint32_t d0, d1, d2, d3;
                ldsm_x4(d0, d1, d2, d3, sw + r * 128 + ((cc ^ (r & 7)) << 4));
                bf[p][2 * j][0] = d0; bf[p][2 * j][1] = d1;
                bf[p][2 * j + 1][0] = d2; bf[p][2 * j + 1][1] = d3;
            }
        };

        ldfrag(0, 0);
#pragma unroll
        for (int ks = 0; ks < 4; ++ks) {
            if (ks < 3) {
                ldfrag(ks + 1, (ks + 1) & 1);
                if (ks == 2 && lane == 0)
                    MBARRIER_ARRIVE(mbe + (c % 3) * 8);
            }
            const int p = ks & 1;
#pragma unroll
            for (int mt = 0; mt < 4; ++mt)
#pragma unroll
                for (int nt = 0; nt < 4; ++nt)
                    mma_f16(acc[mt][nt], af[p][mt][0], af[p][mt][1], af[p][mt][2], af[p][mt][3],
                            bf[p][nt][0], bf[p][nt][1]);
        }

        if (tid == 0 && c + 3 < G_NCH) {
            MBARRIER_WAIT_PARITY(mbe + (c % 3) * 8, (c / 3) & 1);
            produce(c + 3);
        }
    }

    // Epilogue
#pragma unroll
    for (int mt = 0; mt < 4; ++mt) {
#pragma unroll
        for (int nt = 0; nt < 4; ++nt) {
            const int r0 = m0 + wm * 64 + mt * 16 + g;
            const int col = n0 + wn * 32 + nt * 8 + 2 * t;
            if (MODE == 0) {
                *(float2*)(C + (size_t)r0 * EE + col) =
                    make_float2(acc[mt][nt][0], acc[mt][nt][1]);
                *(float2*)(C + (size_t)(r0 + 8) * EE + col) =
                    make_float2(acc[mt][nt][2], acc[mt][nt][3]);
            } else {
                const int which = col >> 10;
                const int rem = col & 1023;
                const int h = rem >> 6;
                const int d = rem & 63;
#pragma unroll
                for (int half = 0; half < 2; ++half) {
                    const int row = r0 + half * 8;
                    const float v0 = acc[mt][nt][2 * half];
                    const float v1 = acc[mt][nt][2 * half + 1];
                    const int bh = (row >> 11) * HH + h;
                    const int tt = row & 2047;
                    if (which == 0) {
                        *(uint32_t*)(g_qh + ((size_t)bh * TT + tt) * DD + d) =
                            f2h2(v0 * QSCALE, v1 * QSCALE);
                    } else if (which == 1) {
                        *(uint32_t*)(g_kh + ((size_t)bh * TT + tt) * DD + d) =
                            f2h2(v0, v1);
                    } else {
                        g_vth[((size_t)bh * DD + d) * TT + tt]     = __float2half(v0);
                        g_vth[((size_t)bh * DD + d + 1) * TT + tt] = __float2half(v1);
                    }
                }
            }
        }
    }
}

// ---------------------------------------------------------------------------
// Causal flash attention — R10 configuration (validated 6.508952e-4):
// q-tile 128, kv-tile 64, 8 warps x 16 q-rows, 2 CTAs/SM, SMEM-P roundtrip,
// Q fragments hoisted, 3-stage kv TMA pipeline, log2-domain softmax.
// SMEM (from aligned base):
//   0      : barriers (q_full @0, kv_full @8..31, kv_empty @32..55)
//   1024   : Q   (128 x 128B = 16KB)
//   17408  : P   (128 x 128B = 16KB)
//   33792  : K/VT stages (3 x 16KB: K 8KB + VT 8KB each)
// ---------------------------------------------------------------------------
#define FA_Q_OFF   1024
#define FA_P_OFF   (FA_Q_OFF + 16384)
#define FA_KV_OFF  (FA_P_OFF + 16384)
#define FA_SMEM_BYTES (FA_KV_OFF + 3 * 16384 + 1024)

__global__ __launch_bounds__(256, 2)
void flash_attn_tma(const __grid_constant__ CUtensorMap tmQ,
                    const __grid_constant__ CUtensorMap tmK,
                    const __grid_constant__ CUtensorMap tmVT)
{
    extern __shared__ char smraw[];
    uint32_t sb = smem_u32(smraw);
    sb = (sb + 1023u) & ~1023u;

    const int qt = gridDim.x - 1 - blockIdx.x;   // long tiles first
    const int bh = blockIdx.y;
    const int q0 = qt * 128;

    const int tid = threadIdx.x, lane = tid & 31, wid = tid >> 5;
    const int g = lane >> 2, t = lane & 3;
    const int wrow = wid * 16;

    const uint32_t qb  = sb + FA_Q_OFF;
    const uint32_t pb  = sb + FA_P_OFF;
    const uint32_t kvb = sb + FA_KV_OFF;
    const uint32_t mbf = sb + 8;    // kv full @ 8,16,24
    const uint32_t mbe = sb + 32;   // kv empty @ 32,40,48

    if (tid == 0) {
        MBARRIER_INIT(sb + 0, 1);
#pragma unroll
        for (int s = 0; s < 3; ++s) {
            MBARRIER_INIT(mbf + s * 8, 1);
            MBARRIER_INIT(mbe + s * 8, 8);
        }
    }
    __syncthreads();

    auto produce_kv = [&](int kt) {
        const int s = kt % 3;
        const int k0 = kt * 64;
        MBARRIER_EXPECT_TX(mbf + s * 8, 16384);
        TMA_LOAD_2D(kvb + s * 16384,        &tmK,  0,  bh * TT + k0, mbf + s * 8);
        TMA_LOAD_2D(kvb + s * 16384 + 8192, &tmVT, k0, bh * 64,      mbf + s * 8);
    };

    const int ktmax = 2 * qt + 1;
    if (tid == 0) {
        MBARRIER_EXPECT_TX(sb + 0, 16384);
        TMA_LOAD_2D(qb, &tmQ, 0, bh * TT + q0, sb + 0);
        produce_kv(0);
        produce_kv(1);
        produce_kv(2);
    }
    MBARRIER_WAIT_PARITY(sb + 0, 0);

    // Hoist Q fragments (constant across kv tiles)
    uint32_t qa[4][4];
#pragma unroll
    for (int ks = 0; ks < 4; ++ks) {
        const int r = wrow + (lane & 7) + ((lane >> 3) & 1) * 8;
        const int cc = ks * 2 + (lane >> 4);
        ldsm_x4(qa[ks][0], qa[ks][1], qa[ks][2], qa[ks][3],
                qb + r * 128 + ((cc ^ (r & 7)) << 4));
    }

    float o[8][4];
#pragma unroll
    for (int nt = 0; nt < 8; ++nt)
#pragma unroll
        for (int j = 0; j < 4; ++j) o[nt][j] = 0.f;
    float mr0 = -INFINITY, mr1 = -INFINITY, lr0 = 0.f, lr1 = 0.f;

    for (int kt = 0; kt <= ktmax; ++kt) {
        const int s3 = kt % 3;
        const int ph = (kt / 3) & 1;
        MBARRIER_WAIT_PARITY(mbf + s3 * 8, ph);

        const int k0 = kt * 64;
        const bool active = (k0 <= q0 + wrow + 15);

        if (active) {
            const uint32_t ks_b = kvb + s3 * 16384;
            const uint32_t vt_b = ks_b + 8192;

            // --- S = Q K^T (Q from registers) ---
            float s[8][4];
#pragma unroll
            for (int nt = 0; nt < 8; ++nt)
#pragma unroll
                for (int j = 0; j < 4; ++j) s[nt][j] = 0.f;

#pragma unroll
            for (int ks = 0; ks < 4; ++ks) {
                const int kc2 = ks * 2;
                uint32_t b[8][2];
#pragma unroll
                for (int j = 0; j < 4; ++j) {
                    const int r = (j * 2 + ((lane >> 4) & 1)) * 8 + (lane & 7);
                    const int cc = kc2 + ((lane >> 3) & 1);
                    uint32_t d0, d1, d2, d3;
                    ldsm_x4(d0, d1, d2, d3, ks_b + r * 128 + ((cc ^ (r & 7)) << 4));
                    b[2 * j][0] = d0; b[2 * j][1] = d1;
                    b[2 * j + 1][0] = d2; b[2 * j + 1][1] = d3;
                }
#pragma unroll
                for (int nt = 0; nt < 8; ++nt)
                    mma_f16(s[nt], qa[ks][0], qa[ks][1], qa[ks][2], qa[ks][3],
                            b[nt][0], b[nt][1]);
            }

            // --- causal mask (diagonal region only) ---
            if (k0 + 63 > q0 + wrow) {
                const int rlo = q0 + wrow + g;
#pragma unroll
                for (int nt = 0; nt < 8; ++nt) {
                    const int key = k0 + nt * 8 + 2 * t;
                    if (key > rlo)         s[nt][0] = -INFINITY;
                    if (key + 1 > rlo)     s[nt][1] = -INFINITY;
                    if (key > rlo + 8)     s[nt][2] = -INFINITY;
                    if (key + 1 > rlo + 8) s[nt][3] = -INFINITY;
                }
            }

            // --- online softmax (log2 domain) + P store (fp16, swizzled) ---
            float mx0 = -INFINITY, mx1 = -INFINITY;
#pragma unroll
            for (int nt = 0; nt < 8; ++nt) {
                mx0 = fmaxf(mx0, fmaxf(s[nt][0], s[nt][1]));
                mx1 = fmaxf(mx1, fmaxf(s[nt][2], s[nt][3]));
            }
            mx0 = fmaxf(mx0, __shfl_xor_sync(0xffffffffu, mx0, 1));
            mx0 = fmaxf(mx0, __shfl_xor_sync(0xffffffffu, mx0, 2));
            mx1 = fmaxf(mx1, __shfl_xor_sync(0xffffffffu, mx1, 1));
            mx1 = fmaxf(mx1, __shfl_xor_sync(0xffffffffu, mx1, 2));

            const float mn0 = fmaxf(mr0, mx0);
            const float mn1 = fmaxf(mr1, mx1);
            const float al0 = ex2f(mr0 - mn0);
            const float al1 = ex2f(mr1 - mn1);
            mr0 = mn0; mr1 = mn1;

            float s0 = 0.f, s1 = 0.f;
#pragma unroll
            for (int nt = 0; nt < 8; ++nt) {
                s[nt][0] = ex2f(s[nt][0] - mn0);
                s[nt][1] = ex2f(s[nt][1] - mn0);
                s[nt][2] = ex2f(s[nt][2] - mn1);
                s[nt][3] = ex2f(s[nt][3] - mn1);
                s0 += s[nt][0] + s[nt][1];
                s1 += s[nt][2] + s[nt][3];
            }
            s0 += __shfl_xor_sync(0xffffffffu, s0, 1);
            s0 += __shfl_xor_sync(0xffffffffu, s0, 2);
            s1 += __shfl_xor_sync(0xffffffffu, s1, 1);
            s1 += __shfl_xor_sync(0xffffffffu, s1, 2);

            lr0 = lr0 * al0 + s0;
            lr1 = lr1 * al1 + s1;
#pragma unroll
            for (int nt = 0; nt < 8; ++nt) {
                o[nt][0] *= al0; o[nt][1] *= al0;
                o[nt][2] *= al1; o[nt][3] *= al1;
            }

#pragma unroll
            for (int half = 0; half < 2; ++half) {
                const int pr = wrow + g + half * 8;
#pragma unroll
                for (int nt = 0; nt < 8; ++nt) {
                    const uint32_t addr = pb + pr * 128 +
                                          ((nt ^ (pr & 7)) << 4) + 4 * t;
                    const uint32_t val = f2h2(s[nt][2 * half], s[nt][2 * half + 1]);
                    asm volatile("st.shared.b32 [%0], %1;"
                                 :: "r"(addr), "r"(val) : "memory");
                }
            }
            __syncwarp();

            // --- O += P V (P from SMEM, proven path) ---
#pragma unroll
            for (int ks = 0; ks < 4; ++ks) {
                const int kc2 = ks * 2;
                uint32_t a[4];
                {
                    const int r = wrow + (lane & 7) + ((lane >> 3) & 1) * 8;
                    const int cc = kc2 + (lane >> 4);
                    ldsm_x4(a[0], a[1], a[2], a[3],
                            pb + r * 128 + ((cc ^ (r & 7)) << 4));
                }
                uint32_t b[8][2];
#pragma unroll
                for (int j = 0; j < 4; ++j) {
                    const int r = (j * 2 + ((lane >> 4) & 1)) * 8 + (lane & 7);
                    const int cc = kc2 + ((lane >> 3) & 1);
                    uint32_t d0, d1, d2, d3;
                    ldsm_x4(d0, d1, d2, d3, vt_b + r * 128 + ((cc ^ (r & 7)) << 4));
                    b[2 * j][0] = d0; b[2 * j][1] = d1;
                    b[2 * j + 1][0] = d2; b[2 * j + 1][1] = d3;
                }
#pragma unroll
                for (int nt = 0; nt < 8; ++nt)
                    mma_f16(o[nt], a[0], a[1], a[2], a[3], b[nt][0], b[nt][1]);
            }
        }

        if (lane == 0) MBARRIER_ARRIVE(mbe + s3 * 8);

        if (tid == 0 && kt + 3 <= ktmax) {
            MBARRIER_WAIT_PARITY(mbe + s3 * 8, ph);
            produce_kv(kt + 3);
        }
    }

    // --- epilogue: normalize, write fp16 att [B,T,E] ---
    const int b = bh >> 4, h = bh & 15;
#pragma unroll
    for (int half = 0; half < 2; ++half) {
        const int row = q0 + wrow + g + half * 8;
        const float inv = 1.0f / (half ? lr1 : lr0);
#pragma unroll
        for (int nt = 0; nt < 8; ++nt) {
            const int col = h * 64 + nt * 8 + 2 * t;
            *(uint32_t*)(g_atth + ((size_t)b * TT + row) * EE + col) =
                f2h2(o[nt][2 * half] * inv, o[nt][2 * half + 1] * inv);
        }
    }
}

// ---------------------------------------------------------------------------
// Host
// ---------------------------------------------------------------------------
typedef CUresult (*EncodeFn)(CUtensorMap*, CUtensorMapDataType, cuuint32_t, void*,
                             const cuuint64_t*, const cuuint64_t*, const cuuint32_t*,
                             const cuuint32_t*, CUtensorMapInterleave, CUtensorMapSwizzle,
                             CUtensorMapL2promotion, CUtensorMapFloatOOBfill);

static void make_tm(EncodeFn enc, CUtensorMap* tm, void* ptr,
                    uint64_t d0, uint64_t d1, uint32_t b0, uint32_t b1)
{
    cuuint64_t dims[2]    = {d0, d1};
    cuuint64_t strides[1] = {d0 * 2};
    cuuint32_t box[2]     = {b0, b1};
    cuuint32_t estr[2]    = {1, 1};
    enc(tm, CU_TENSOR_MAP_DATA_TYPE_FLOAT16, 2, ptr, dims, strides, box, estr,
        CU_TENSOR_MAP_INTERLEAVE_NONE, CU_TENSOR_MAP_SWIZZLE_128B,
        CU_TENSOR_MAP_L2_PROMOTION_L2_128B, CU_TENSOR_MAP_FLOAT_OOB_FILL_NONE);
}

extern "C" void kernel_launch(void* const* d_in, const int* in_sizes, int n_in,
                              void* d_out, int out_size)
{
    const float* x    = (const float*)d_in[0];   // [B,T,E]
    const float* Wqkv = (const float*)d_in[1];   // [3E,E]
    const float* Wout = (const float*)d_in[2];   // [E,E]
    float* out = (float*)d_out;                  // [B,T,E]

    void *xh, *wqkvh, *wouth, *atth, *qp, *kp, *vtp;
    cudaGetSymbolAddress(&xh, g_xh);
    cudaGetSymbolAddress(&wqkvh, g_wqkvh);
    cudaGetSymbolAddress(&wouth, g_wouth);
    cudaGetSymbolAddress(&atth, g_atth);
    cudaGetSymbolAddress(&qp, g_qh);
    cudaGetSymbolAddress(&kp, g_kh);
    cudaGetSymbolAddress(&vtp, g_vth);

    void* pf = nullptr;
    cudaDriverEntryPointQueryResult qr;
    cudaGetDriverEntryPoint("cuTensorMapEncodeTiled", &pf, cudaEnableDefault, &qr);
    EncodeFn enc = (EncodeFn)pf;

    CUtensorMap tmX, tmWqkv, tmAtt, tmWout, tmQ, tmK, tmVT;
    make_tm(enc, &tmX,    xh,    1024, MROWS,               64, 128);
    make_tm(enc, &tmWqkv, wqkvh, 1024, 3072,                64, 128);
    make_tm(enc, &tmAtt,  atth,  1024, MROWS,               64, 128);
    make_tm(enc, &tmWout, wouth, 1024, 1024,                64, 128);
    make_tm(enc, &tmQ,    qp,    64,   (uint64_t)BB * HH * TT, 64, 128);
    make_tm(enc, &tmK,    kp,    64,   (uint64_t)BB * HH * TT, 64, 64);
    make_tm(enc, &tmVT,   vtp,   2048, (uint64_t)BB * HH * DD, 64, 64);

    cudaFuncSetAttribute(gemm_tma<0>, cudaFuncAttributeMaxDynamicSharedMemorySize, GEMM_SMEM_BYTES);
    cudaFuncSetAttribute(gemm_tma<1>, cudaFuncAttributeMaxDynamicSharedMemorySize, GEMM_SMEM_BYTES);
    cudaFuncSetAttribute(flash_attn_tma, cudaFuncAttributeMaxDynamicSharedMemorySize, FA_SMEM_BYTES);

    // 0) convert operands to fp16 (three separate launches — R10-proven)
    {
        int n4 = MROWS * EE / 4;
        conv_half<<<(n4 + 255) / 256, 256>>>((const float4*)x, (uint2*)xh, n4);
        n4 = 3 * EE * EE / 4;
        conv_half<<<(n4 + 255) / 256, 256>>>((const float4*)Wqkv, (uint2*)wqkvh, n4);
        n4 = EE * EE / 4;
        conv_half<<<(n4 + 255) / 256, 256>>>((const float4*)Wout, (uint2*)wouth, n4);
    }

    // 1) QKV projection + scatter (q scaled, v transposed)
    {
        dim3 grid(3 * EE / 128, MROWS / 128);   // (24, 64)
        gemm_tma<1><<<grid, 256, GEMM_SMEM_BYTES>>>(tmX, tmWqkv, nullptr);
    }

    // 2) Causal flash attention -> g_atth (fp16)
    {
        dim3 grid(TT / 128, BB * HH);           // (16, 64)
        flash_attn_tma<<<grid, 256, FA_SMEM_BYTES>>>(tmQ, tmK, tmVT);
    }

    // 3) Output projection (fp32 out)
    {
        dim3 grid(EE / 128, MROWS / 128);       // (8, 64)
        gemm_tma<0><<<grid, 256, GEMM_SMEM_BYTES>>>(tmAtt, tmWout, out);
    }
}

// round 14
// speedup vs baseline: 1.1342x; 1.0130x over previous
#include <cuda_runtime.h>
#include <cuda.h>
#include <cuda_fp16.h>
#include <math.h>
#include <stdint.h>

#define BB 4
#define TT 2048
#define EE 1024
#define HH 16
#define DD 64
#define MROWS (BB * TT)   // 8192

// ---------------------------------------------------------------------------
// Scratch (__device__ globals; allocation-free rule) — fp16 operands
// ---------------------------------------------------------------------------
__device__ __half g_xh[(size_t)MROWS * EE];
__device__ __half g_wqkvh[(size_t)3 * EE * EE];
__device__ __half g_wouth[(size_t)EE * EE];
__device__ __half g_qh[(size_t)BB * HH * TT * DD];  // scaled Q [bh][t][d]
__device__ __half g_kh[(size_t)BB * HH * TT * DD];  // K [bh][t][d]
__device__ __half g_vth[(size_t)BB * HH * DD * TT]; // V^T [bh][d][t]
__device__ __half g_atth[(size_t)MROWS * EE];       // attention out

// ---------------------------------------------------------------------------
// Helpers
// ---------------------------------------------------------------------------
__device__ __forceinline__ float ex2f(float x) {
    float y;
    asm("ex2.approx.f32 %0, %1;" : "=f"(y) : "f"(x));
    return y;
}

__device__ __forceinline__ uint32_t f2h2(float lo, float hi) {
    __half2 h = __floats2half2_rn(lo, hi);
    return *(uint32_t*)&h;
}

__device__ __forceinline__ void mma_f16(float c[4],
                                        uint32_t a0, uint32_t a1, uint32_t a2, uint32_t a3,
                                        uint32_t b0, uint32_t b1) {
    asm volatile(
        "mma.sync.aligned.m16n8k16.row.col.f32.f16.f16.f32 "
        "{%0,%1,%2,%3}, {%4,%5,%6,%7}, {%8,%9}, {%0,%1,%2,%3};\n"
        : "+f"(c[0]), "+f"(c[1]), "+f"(c[2]), "+f"(c[3])
        : "r"(a0), "r"(a1), "r"(a2), "r"(a3), "r"(b0), "r"(b1));
}

__device__ __forceinline__ void ldsm_x4(uint32_t& d0, uint32_t& d1, uint32_t& d2, uint32_t& d3,
                                        uint32_t addr) {
    asm volatile("ldmatrix.sync.aligned.m8n8.x4.shared.b16 {%0,%1,%2,%3}, [%4];"
                 : "=r"(d0), "=r"(d1), "=r"(d2), "=r"(d3) : "r"(addr));
}

__device__ __forceinline__ uint32_t smem_u32(const void* p) {
    uint32_t a;
    asm("{ .reg .u64 t; cvta.to.shared.u64 t, %1; cvt.u32.u64 %0, t; }"
        : "=r"(a) : "l"(p));
    return a;
}

#define MBARRIER_INIT(addr, cnt) \
    asm volatile("mbarrier.init.shared.b64 [%0], %1;" :: "r"((uint32_t)(addr)), "r"((uint32_t)(cnt)) : "memory")

#define MBARRIER_ARRIVE(addr) \
    asm volatile("mbarrier.arrive.release.cta.shared.b64 _, [%0];" :: "r"((uint32_t)(addr)) : "memory")

#define MBARRIER_EXPECT_TX(addr, bytes) \
    asm volatile("mbarrier.arrive.expect_tx.shared.b64 _, [%0], %1;" :: "r"((uint32_t)(addr)), "r"((uint32_t)(bytes)) : "memory")

#define MBARRIER_WAIT_PARITY(addr, parity) do {                                   \
    uint32_t _mb = (uint32_t)(addr);                                              \
    uint32_t _ph = (uint32_t)(parity);                                            \
    uint32_t _done;                                                               \
    asm volatile("{\n\t.reg .pred p;\n\t"                                         \
        "mbarrier.try_wait.parity.acquire.cta.shared::cta.b64 p, [%1], %2;\n\t"   \
        "selp.b32 %0, 1, 0, p;\n\t}"                                              \
        : "=r"(_done) : "r"(_mb), "r"(_ph) : "memory");                           \
    if (!_done) {                                                                 \
        asm volatile("{\n\t.reg .pred P1;\n\t"                                    \
            "WAIT_LOOP_%=:\n\t"                                                   \
            "mbarrier.try_wait.parity.acquire.cta.shared::cta.b64 P1, [%0], %1, 0x989680;\n\t" \
            "@P1 bra.uni WAIT_DONE_%=;\n\t"                                       \
            "bra.uni WAIT_LOOP_%=;\n\t"                                           \
            "WAIT_DONE_%=:\n\t}"                                                  \
            :: "r"(_mb), "r"(_ph) : "memory");                                    \
    }                                                                             \
} while (0)

#define TMA_LOAD_2D(smem_addr, map_ptr, cx, cy, mbar) \
    asm volatile("cp.async.bulk.tensor.2d.shared::cta.global.tile.mbarrier::complete_tx::bytes " \
                 "[%0], [%1, {%2, %3}], [%4];" \
                 :: "r"((uint32_t)(smem_addr)), "l"(map_ptr), \
                    "r"((int32_t)(cx)), "r"((int32_t)(cy)), "r"((uint32_t)(mbar)) : "memory")

// Q pre-scale: D^-0.5 * log2(e)
#define QSCALE 0.18033688011112042f

// ---------------------------------------------------------------------------
// Prep: fused f32 -> fp16 conversion of all three operand tensors (1 launch)
// ---------------------------------------------------------------------------
#define X_N4    (MROWS * EE / 4)
#define WQKV_N4 (3 * EE * EE / 4)
#define WOUT_N4 (EE * EE / 4)
#define PREP_N4 (X_N4 + WQKV_N4 + WOUT_N4)

__global__ void conv_all(const float4* __restrict__ x,
                         const float4* __restrict__ wqkv,
                         const float4* __restrict__ wout)
{
    int i = blockIdx.x * blockDim.x + threadIdx.x;
    if (i >= PREP_N4) return;
    const float4* src;
    uint2* dst;
    if (i < X_N4) {
        src = x + i;
        dst = (uint2*)g_xh + i;
    } else if (i < X_N4 + WQKV_N4) {
        src = wqkv + (i - X_N4);
        dst = (uint2*)g_wqkvh + (i - X_N4);
    } else {
        src = wout + (i - X_N4 - WQKV_N4);
        dst = (uint2*)g_wouth + (i - X_N4 - WQKV_N4);
    }
    float4 v = *src;
    *dst = make_uint2(f2h2(v.x, v.y), f2h2(v.z, v.w));
}

// ---------------------------------------------------------------------------
// fp16 GEMM (NT): CTA 128x128, BK=64, 16 chunks, 8 warps (2m x 4n),
// warp tile 64x32. 3-stage TMA full/empty pipeline, 2 CTAs/SM.
// RACE FIX: the empty-barrier arrive now executes AFTER the final mma of the
// chunk. The mma's register dependency on the last ldsm forces those SMEM
// reads to complete before the arrive issues (in-order warp issue), so the
// producer can never overwrite a stage that is still being read.
// MODE 0: fp32 row-major store. MODE 1: QKV scatter (q scaled, v transposed).
// ---------------------------------------------------------------------------
#define G_NCH 16
#define G_STAGE_BYTES 32768           // A 128x128B + B 128x128B
#define GEMM_SMEM_BYTES (1024 + 3 * G_STAGE_BYTES)

template <int MODE>
__global__ __launch_bounds__(256, 2)
void gemm_tma(const __grid_constant__ CUtensorMap tmA,
              const __grid_constant__ CUtensorMap tmB,
              float* __restrict__ C)
{
    extern __shared__ char smraw[];
    uint32_t sb = smem_u32(smraw);
    sb = (sb + 1023u) & ~1023u;

    const int tid = threadIdx.x, lane = tid & 31, wid = tid >> 5;
    const int wm = wid & 1, wn = wid >> 1;
    const int g = lane >> 2, t = lane & 3;
    const int m0 = blockIdx.y * 128;
    const int n0 = blockIdx.x * 128;

    const uint32_t mbf = sb;             // full  @ +0,8,16
    const uint32_t mbe = sb + 24;        // empty @ +24,32,40
    const uint32_t st0 = sb + 1024;

    if (tid == 0) {
#pragma unroll
        for (int s = 0; s < 3; ++s) {
            MBARRIER_INIT(mbf + s * 8, 1);
            MBARRIER_INIT(mbe + s * 8, 8);
        }
    }
    __syncthreads();

    auto produce = [&](int c) {
        const int s = c % 3;
        MBARRIER_EXPECT_TX(mbf + s * 8, G_STAGE_BYTES);
        const uint32_t sa = st0 + s * G_STAGE_BYTES;
        TMA_LOAD_2D(sa,         &tmA, c * 64, m0, mbf + s * 8);
        TMA_LOAD_2D(sa + 16384, &tmB, c * 64, n0, mbf + s * 8);
    };

    if (tid == 0) { produce(0); produce(1); produce(2); }

    float acc[4][4][4];
#pragma unroll
    for (int mt = 0; mt < 4; ++mt)
#pragma unroll
        for (int nt = 0; nt < 4; ++nt)
#pragma unroll
            for (int j = 0; j < 4; ++j) acc[mt][nt][j] = 0.f;

    for (int c = 0; c < G_NCH; ++c) {
        MBARRIER_WAIT_PARITY(mbf + (c % 3) * 8, (c / 3) & 1);

        const uint32_t sa = st0 + (c % 3) * G_STAGE_BYTES;
        const uint32_t sw = sa + 16384;

        uint32_t af[2][4][4], bf[2][4][2];
        auto ldfrag = [&](int ks, int p) {
            const int kc2 = ks * 2;
#pragma unroll
            for (int mt = 0; mt < 4; ++mt) {
                const int r = wm * 64 + mt * 16 + (lane & 7) + ((lane >> 3) & 1) * 8;
                const int cc = kc2 + (lane >> 4);
                ldsm_x4(af[p][mt][0], af[p][mt][1], af[p][mt][2], af[p][mt][3],
                        sa + r * 128 + ((cc ^ (r & 7)) << 4));
            }
#pragma unroll
            for (int j = 0; j < 2; ++j) {
                const int r = wn * 32 + (j * 2 + ((lane >> 4) & 1)) * 8 + (lane & 7);
                const int cc = kc2 + ((lane >> 3) & 1);
                uint32_t d0, d1, d2, d3;
                ldsm_x4(d0, d1, d2, d3, sw + r * 128 + ((cc ^ (r & 7)) << 4));
                bf[p][2 * j][0] = d0; bf[p][2 * j][1] = d1;
                bf[p][2 * j + 1][0] = d2; bf[p][2 * j + 1][1] = d3;
            }
        };

        ldfrag(0, 0);
#pragma unroll
        for (int ks = 0; ks < 4; ++ks) {
            if (ks < 3) ldfrag(ks + 1, (ks + 1) & 1);
            const int p = ks & 1;
#pragma unroll
            for (int mt = 0; mt < 4; ++mt)
#pragma unroll
                for (int nt = 0; nt < 4; ++nt)
                    mma_f16(acc[mt][nt], af[p][mt][0], af[p][mt][1], af[p][mt][2], af[p][mt][3],
                            bf[p][nt][0], bf[p][nt][1]);
        }

        // RACE FIX: arrive only after ALL mma of this chunk have issued.
        // The ks=3 mma depends on the last ldsm's destination registers, so
        // every SMEM read of this stage is complete before this point.
        if (lane == 0) MBARRIER_ARRIVE(mbe + (c % 3) * 8);

        if (tid == 0 && c + 3 < G_NCH) {
            MBARRIER_WAIT_PARITY(mbe + (c % 3) * 8, (c / 3) & 1);
            produce(c + 3);
        }
    }

    // Epilogue
#pragma unroll
    for (int mt = 0; mt < 4; ++mt) {
#pragma unroll
        for (int nt = 0; nt < 4; ++nt) {
            const int r0 = m0 + wm * 64 + mt * 16 + g;
            const int col = n0 + wn * 32 + nt * 8 + 2 * t;
            if (MODE == 0) {
                *(float2*)(C + (size_t)r0 * EE + col) =
                    make_float2(acc[mt][nt][0], acc[mt][nt][1]);
                *(float2*)(C + (size_t)(r0 + 8) * EE + col) =
                    make_float2(acc[mt][nt][2], acc[mt][nt][3]);
            } else {
                const int which = col >> 10;
                const int rem = col & 1023;
                const int h = rem >> 6;
                const int d = rem & 63;
#pragma unroll
                for (int half = 0; half < 2; ++half) {
                    const int row = r0 + half * 8;
                    const float v0 = acc[mt][nt][2 * half];
                    const float v1 = acc[mt][nt][2 * half + 1];
                    const int bh = (row >> 11) * HH + h;
                    const int tt = row & 2047;
                    if (which == 0) {
                        *(uint32_t*)(g_qh + ((size_t)bh * TT + tt) * DD + d) =
                            f2h2(v0 * QSCALE, v1 * QSCALE);
                    } else if (which == 1) {
                        *(uint32_t*)(g_kh + ((size_t)bh * TT + tt) * DD + d) =
                            f2h2(v0, v1);
                    } else {
                        g_vth[((size_t)bh * DD + d) * TT + tt]     = __float2half(v0);
                        g_vth[((size_t)bh * DD + d + 1) * TT + tt] = __float2half(v1);
                    }
                }
            }
        }
    }
}

// ---------------------------------------------------------------------------
// Causal flash attention — R10 configuration. (Its empty arrive already sits
// after the PV mma's, so it never had the in-flight-read race.)
// q-tile 128, kv-tile 64, 8 warps x 16 q-rows, 2 CTAs/SM, SMEM-P roundtrip,
// Q fragments hoisted, 3-stage kv TMA pipeline, log2-domain softmax.
// ---------------------------------------------------------------------------
#define FA_Q_OFF   1024
#define FA_P_OFF   (FA_Q_OFF + 16384)
#define FA_KV_OFF  (FA_P_OFF + 16384)
#define FA_SMEM_BYTES (FA_KV_OFF + 3 * 16384 + 1024)

__global__ __launch_bounds__(256, 2)
void flash_attn_tma(const __grid_constant__ CUtensorMap tmQ,
                    const __grid_constant__ CUtensorMap tmK,
                    const __grid_constant__ CUtensorMap tmVT)
{
    extern __shared__ char smraw[];
    uint32_t sb = smem_u32(smraw);
    sb = (sb + 1023u) & ~1023u;

    const int qt = gridDim.x - 1 - blockIdx.x;   // long tiles first
    const int bh = blockIdx.y;
    const int q0 = qt * 128;

    const int tid = threadIdx.x, lane = tid & 31, wid = tid >> 5;
    const int g = lane >> 2, t = lane & 3;
    const int wrow = wid * 16;

    const uint32_t qb  = sb + FA_Q_OFF;
    const uint32_t pb  = sb + FA_P_OFF;
    const uint32_t kvb = sb + FA_KV_OFF;
    const uint32_t mbf = sb + 8;    // kv full @ 8,16,24
    const uint32_t mbe = sb + 32;   // kv empty @ 32,40,48

    if (tid == 0) {
        MBARRIER_INIT(sb + 0, 1);
#pragma unroll
        for (int s = 0; s < 3; ++s) {
            MBARRIER_INIT(mbf + s * 8, 1);
            MBARRIER_INIT(mbe + s * 8, 8);
        }
    }
    __syncthreads();

    auto produce_kv = [&](int kt) {
        const int s = kt % 3;
        const int k0 = kt * 64;
        MBARRIER_EXPECT_TX(mbf + s * 8, 16384);
        TMA_LOAD_2D(kvb + s * 16384,        &tmK,  0,  bh * TT + k0, mbf + s * 8);
        TMA_LOAD_2D(kvb + s * 16384 + 8192, &tmVT, k0, bh * 64,      mbf + s * 8);
    };

    const int ktmax = 2 * qt + 1;
    if (tid == 0) {
        MBARRIER_EXPECT_TX(sb + 0, 16384);
        TMA_LOAD_2D(qb, &tmQ, 0, bh * TT + q0, sb + 0);
        produce_kv(0);
        produce_kv(1);
        produce_kv(2);
    }
    MBARRIER_WAIT_PARITY(sb + 0, 0);

    // Hoist Q fragments (constant across kv tiles)
    uint32_t qa[4][4];
#pragma unroll
    for (int ks = 0; ks < 4; ++ks) {
        const int r = wrow + (lane & 7) + ((lane >> 3) & 1) * 8;
        const int cc = ks * 2 + (lane >> 4);
        ldsm_x4(qa[ks][0], qa[ks][1], qa[ks][2], qa[ks][3],
                qb + r * 128 + ((cc ^ (r & 7)) << 4));
    }

    float o[8][4];
#pragma unroll
    for (int nt = 0; nt < 8; ++nt)
#pragma unroll
        for (int j = 0; j < 4; ++j) o[nt][j] = 0.f;
    float mr0 = -INFINITY, mr1 = -INFINITY, lr0 = 0.f, lr1 = 0.f;

    for (int kt = 0; kt <= ktmax; ++kt) {
        const int s3 = kt % 3;
        const int ph = (kt / 3) & 1;
        MBARRIER_WAIT_PARITY(mbf + s3 * 8, ph);

        const int k0 = kt * 64;
        const bool active = (k0 <= q0 + wrow + 15);

        if (active) {
            const uint32_t ks_b = kvb + s3 * 16384;
            const uint32_t vt_b = ks_b + 8192;

            // --- S = Q K^T (Q from registers) ---
            float s[8][4];
#pragma unroll
            for (int nt = 0; nt < 8; ++nt)
#pragma unroll
                for (int j = 0; j < 4; ++j) s[nt][j] = 0.f;

#pragma unroll
            for (int ks = 0; ks < 4; ++ks) {
                const int kc2 = ks * 2;
                uint32_t b[8][2];
#pragma unroll
                for (int j = 0; j < 4; ++j) {
                    const int r = (j * 2 + ((lane >> 4) & 1)) * 8 + (lane & 7);
                    const int cc = kc2 + ((lane >> 3) & 1);
                    uint32_t d0, d1, d2, d3;
                    ldsm_x4(d0, d1, d2, d3, ks_b + r * 128 + ((cc ^ (r & 7)) << 4));
                    b[2 * j][0] = d0; b[2 * j][1] = d1;
                    b[2 * j + 1][0] = d2; b[2 * j + 1][1] = d3;
                }
#pragma unroll
                for (int nt = 0; nt < 8; ++nt)
                    mma_f16(s[nt], qa[ks][0], qa[ks][1], qa[ks][2], qa[ks][3],
                            b[nt][0], b[nt][1]);
            }

            // --- causal mask (diagonal region only) ---
            if (k0 + 63 > q0 + wrow) {
                const int rlo = q0 + wrow + g;
#pragma unroll
                for (int nt = 0; nt < 8; ++nt) {
                    const int key = k0 + nt * 8 + 2 * t;
                    if (key > rlo)         s[nt][0] = -INFINITY;
                    if (key + 1 > rlo)     s[nt][1] = -INFINITY;
                    if (key > rlo + 8)     s[nt][2] = -INFINITY;
                    if (key + 1 > rlo + 8) s[nt][3] = -INFINITY;
                }
            }

            // --- online softmax (log2 domain) + P store (fp16, swizzled) ---
            float mx0 = -INFINITY, mx1 = -INFINITY;
#pragma unroll
            for (int nt = 0; nt < 8; ++nt) {
                mx0 = fmaxf(mx0, fmaxf(s[nt][0], s[nt][1]));
                mx1 = fmaxf(mx1, fmaxf(s[nt][2], s[nt][3]));
            }
            mx0 = fmaxf(mx0, __shfl_xor_sync(0xffffffffu, mx0, 1));
            mx0 = fmaxf(mx0, __shfl_xor_sync(0xffffffffu, mx0, 2));
            mx1 = fmaxf(mx1, __shfl_xor_sync(0xffffffffu, mx1, 1));
            mx1 = fmaxf(mx1, __shfl_xor_sync(0xffffffffu, mx1, 2));

            const float mn0 = fmaxf(mr0, mx0);
            const float mn1 = fmaxf(mr1, mx1);
            const float al0 = ex2f(mr0 - mn0);
            const float al1 = ex2f(mr1 - mn1);
            mr0 = mn0; mr1 = mn1;

            float s0 = 0.f, s1 = 0.f;
#pragma unroll
            for (int nt = 0; nt < 8; ++nt) {
                s[nt][0] = ex2f(s[nt][0] - mn0);
                s[nt][1] = ex2f(s[nt][1] - mn0);
                s[nt][2] = ex2f(s[nt][2] - mn1);
                s[nt][3] = ex2f(s[nt][3] - mn1);
                s0 += s[nt][0] + s[nt][1];
                s1 += s[nt][2] + s[nt][3];
            }
            s0 += __shfl_xor_sync(0xffffffffu, s0, 1);
            s0 += __shfl_xor_sync(0xffffffffu, s0, 2);
            s1 += __shfl_xor_sync(0xffffffffu, s1, 1);
            s1 += __shfl_xor_sync(0xffffffffu, s1, 2);

            lr0 = lr0 * al0 + s0;
            lr1 = lr1 * al1 + s1;
#pragma unroll
            for (int nt = 0; nt < 8; ++nt) {
                o[nt][0] *= al0; o[nt][1] *= al0;
                o[nt][2] *= al1; o[nt][3] *= al1;
            }

#pragma unroll
            for (int half = 0; half < 2; ++half) {
                const int pr = wrow + g + half * 8;
#pragma unroll
                for (int nt = 0; nt < 8; ++nt) {
                    const uint32_t addr = pb + pr * 128 +
                                          ((nt ^ (pr & 7)) << 4) + 4 * t;
                    const uint32_t val = f2h2(s[nt][2 * half], s[nt][2 * half + 1]);
                    asm volatile("st.shared.b32 [%0], %1;"
                                 :: "r"(addr), "r"(val) : "memory");
                }
            }
            __syncwarp();

            // --- O += P V (P from SMEM, proven path) ---
#pragma unroll
            for (int ks = 0; ks < 4; ++ks) {
                const int kc2 = ks * 2;
                uint32_t a[4];
                {
                    const int r = wrow + (lane & 7) + ((lane >> 3) & 1) * 8;
                    const int cc = kc2 + (lane >> 4);
                    ldsm_x4(a[0], a[1], a[2], a[3],
                            pb + r * 128 + ((cc ^ (r & 7)) << 4));
                }
                uint32_t b[8][2];
#pragma unroll
                for (int j = 0; j < 4; ++j) {
                    const int r = (j * 2 + ((lane >> 4) & 1)) * 8 + (lane & 7);
                    const int cc = kc2 + ((lane >> 3) & 1);
                    uint32_t d0, d1, d2, d3;
                    ldsm_x4(d0, d1, d2, d3, vt_b + r * 128 + ((cc ^ (r & 7)) << 4));
                    b[2 * j][0] = d0; b[2 * j][1] = d1;
                    b[2 * j + 1][0] = d2; b[2 * j + 1][1] = d3;
                }
#pragma unroll
                for (int nt = 0; nt < 8; ++nt)
                    mma_f16(o[nt], a[0], a[1], a[2], a[3], b[nt][0], b[nt][1]);
            }
        }

        if (lane == 0) MBARRIER_ARRIVE(mbe + s3 * 8);

        if (tid == 0 && kt + 3 <= ktmax) {
            MBARRIER_WAIT_PARITY(mbe + s3 * 8, ph);
            produce_kv(kt + 3);
        }
    }

    // --- epilogue: normalize, write fp16 att [B,T,E] ---
    const int b = bh >> 4, h = bh & 15;
#pragma unroll
    for (int half = 0; half < 2; ++half) {
        const int row = q0 + wrow + g + half * 8;
        const float inv = 1.0f / (half ? lr1 : lr0);
#pragma unroll
        for (int nt = 0; nt < 8; ++nt) {
            const int col = h * 64 + nt * 8 + 2 * t;
            *(uint32_t*)(g_atth + ((size_t)b * TT + row) * EE + col) =
                f2h2(o[nt][2 * half] * inv, o[nt][2 * half + 1] * inv);
        }
    }
}

// ---------------------------------------------------------------------------
// Host
// ---------------------------------------------------------------------------
typedef CUresult (*EncodeFn)(CUtensorMap*, CUtensorMapDataType, cuuint32_t, void*,
                             const cuuint64_t*, const cuuint64_t*, const cuuint32_t*,
                             const cuuint32_t*, CUtensorMapInterleave, CUtensorMapSwizzle,
                             CUtensorMapL2promotion, CUtensorMapFloatOOBfill);

static void make_tm(EncodeFn enc, CUtensorMap* tm, void* ptr,
                    uint64_t d0, uint64_t d1, uint32_t b0, uint32_t b1)
{
    cuuint64_t dims[2]    = {d0, d1};
    cuuint64_t strides[1] = {d0 * 2};
    cuuint32_t box[2]     = {b0, b1};
    cuuint32_t estr[2]    = {1, 1};
    enc(tm, CU_TENSOR_MAP_DATA_TYPE_FLOAT16, 2, ptr, dims, strides, box, estr,
        CU_TENSOR_MAP_INTERLEAVE_NONE, CU_TENSOR_MAP_SWIZZLE_128B,
        CU_TENSOR_MAP_L2_PROMOTION_L2_128B, CU_TENSOR_MAP_FLOAT_OOB_FILL_NONE);
}

extern "C" void kernel_launch(void* const* d_in, const int* in_sizes, int n_in,
                              void* d_out, int out_size)
{
    const float* x    = (const float*)d_in[0];   // [B,T,E]
    const float* Wqkv = (const float*)d_in[1];   // [3E,E]
    const float* Wout = (const float*)d_in[2];   // [E,E]
    float* out = (float*)d_out;                  // [B,T,E]

    void *xh, *wqkvh, *wouth, *atth, *qp, *kp, *vtp;
    cudaGetSymbolAddress(&xh, g_xh);
    cudaGetSymbolAddress(&wqkvh, g_wqkvh);
    cudaGetSymbolAddress(&wouth, g_wouth);
    cudaGetSymbolAddress(&atth, g_atth);
    cudaGetSymbolAddress(&qp, g_qh);
    cudaGetSymbolAddress(&kp, g_kh);
    cudaGetSymbolAddress(&vtp, g_vth);

    void* pf = nullptr;
    cudaDriverEntryPointQueryResult qr;
    cudaGetDriverEntryPoint("cuTensorMapEncodeTiled", &pf, cudaEnableDefault, &qr);
    EncodeFn enc = (EncodeFn)pf;

    CUtensorMap tmX, tmWqkv, tmAtt, tmWout, tmQ, tmK, tmVT;
    make_tm(enc, &tmX,    xh,    1024, MROWS,               64, 128);
    make_tm(enc, &tmWqkv, wqkvh, 1024, 3072,                64, 128);
    make_tm(enc, &tmAtt,  atth,  1024, MROWS,               64, 128);
    make_tm(enc, &tmWout, wouth, 1024, 1024,                64, 128);
    make_tm(enc, &tmQ,    qp,    64,   (uint64_t)BB * HH * TT, 64, 128);
    make_tm(enc, &tmK,    kp,    64,   (uint64_t)BB * HH * TT, 64, 64);
    make_tm(enc, &tmVT,   vtp,   2048, (uint64_t)BB * HH * DD, 64, 64);

    cudaFuncSetAttribute(gemm_tma<0>, cudaFuncAttributeMaxDynamicSharedMemorySize, GEMM_SMEM_BYTES);
    cudaFuncSetAttribute(gemm_tma<1>, cudaFuncAttributeMaxDynamicSharedMemorySize, GEMM_SMEM_BYTES);
    cudaFuncSetAttribute(flash_attn_tma, cudaFuncAttributeMaxDynamicSharedMemorySize, FA_SMEM_BYTES);

    // 0) convert all operands to fp16 in one launch
    conv_all<<<(PREP_N4 + 255) / 256, 256>>>((const float4*)x, (const float4*)Wqkv,
                                             (const float4*)Wout);

    // 1) QKV projection + scatter (q scaled, v transposed)
    {
        dim3 grid(3 * EE / 128, MROWS / 128);   // (24, 64)
        gemm_tma<1><<<grid, 256, GEMM_SMEM_BYTES>>>(tmX, tmWqkv, nullptr);
    }

    // 2) Causal flash attention -> g_atth (fp16)
    {
        dim3 grid(TT / 128, BB * HH);           // (16, 64)
        flash_attn_tma<<<grid, 256, FA_SMEM_BYTES>>>(tmQ, tmK, tmVT);
    }

    // 3) Output projection (fp32 out)
    {
        dim3 grid(EE / 128, MROWS / 128);       // (8, 64)
        gemm_tma<0><<<grid, 256, GEMM_SMEM_BYTES>>>(tmAtt, tmWout, out);
    }
}

// round 16
// speedup vs baseline: 1.1380x; 1.0034x over previous
#include <cuda_runtime.h>
#include <cuda.h>
#include <cuda_fp16.h>
#include <math.h>
#include <stdint.h>

#define BB 4
#define TT 2048
#define EE 1024
#define HH 16
#define DD 64
#define MROWS (BB * TT)   // 8192

// ---------------------------------------------------------------------------
// Scratch (__device__ globals; allocation-free rule) — fp16 operands
// ---------------------------------------------------------------------------
__device__ __half g_xh[(size_t)MROWS * EE];
__device__ __half g_wqkvh[(size_t)3 * EE * EE];
__device__ __half g_wouth[(size_t)EE * EE];
__device__ __half g_qh[(size_t)BB * HH * TT * DD];  // scaled Q [bh][t][d]
__device__ __half g_kh[(size_t)BB * HH * TT * DD];  // K [bh][t][d]
__device__ __half g_vth[(size_t)BB * HH * DD * TT]; // V^T [bh][d][t]
__device__ __half g_atth[(size_t)MROWS * EE];       // attention out

// ---------------------------------------------------------------------------
// Helpers
// ---------------------------------------------------------------------------
__device__ __forceinline__ float ex2f(float x) {
    float y;
    asm("ex2.approx.f32 %0, %1;" : "=f"(y) : "f"(x));
    return y;
}

__device__ __forceinline__ uint32_t f2h2(float lo, float hi) {
    __half2 h = __floats2half2_rn(lo, hi);
    return *(uint32_t*)&h;
}

__device__ __forceinline__ void mma_f16(float c[4],
                                        uint32_t a0, uint32_t a1, uint32_t a2, uint32_t a3,
                                        uint32_t b0, uint32_t b1) {
    asm volatile(
        "mma.sync.aligned.m16n8k16.row.col.f32.f16.f16.f32 "
        "{%0,%1,%2,%3}, {%4,%5,%6,%7}, {%8,%9}, {%0,%1,%2,%3};\n"
        : "+f"(c[0]), "+f"(c[1]), "+f"(c[2]), "+f"(c[3])
        : "r"(a0), "r"(a1), "r"(a2), "r"(a3), "r"(b0), "r"(b1));
}

__device__ __forceinline__ void ldsm_x4(uint32_t& d0, uint32_t& d1, uint32_t& d2, uint32_t& d3,
                                        uint32_t addr) {
    asm volatile("ldmatrix.sync.aligned.m8n8.x4.shared.b16 {%0,%1,%2,%3}, [%4];"
                 : "=r"(d0), "=r"(d1), "=r"(d2), "=r"(d3) : "r"(addr));
}

__device__ __forceinline__ uint32_t smem_u32(const void* p) {
    uint32_t a;
    asm("{ .reg .u64 t; cvta.to.shared.u64 t, %1; cvt.u32.u64 %0, t; }"
        : "=r"(a) : "l"(p));
    return a;
}

#define MBARRIER_INIT(addr, cnt) \
    asm volatile("mbarrier.init.shared.b64 [%0], %1;" :: "r"((uint32_t)(addr)), "r"((uint32_t)(cnt)) : "memory")

#define MBARRIER_ARRIVE(addr) \
    asm volatile("mbarrier.arrive.release.cta.shared.b64 _, [%0];" :: "r"((uint32_t)(addr)) : "memory")

#define MBARRIER_EXPECT_TX(addr, bytes) \
    asm volatile("mbarrier.arrive.expect_tx.shared.b64 _, [%0], %1;" :: "r"((uint32_t)(addr)), "r"((uint32_t)(bytes)) : "memory")

#define MBARRIER_WAIT_PARITY(addr, parity) do {                                   \
    uint32_t _mb = (uint32_t)(addr);                                              \
    uint32_t _ph = (uint32_t)(parity);                                            \
    uint32_t _done;                                                               \
    asm volatile("{\n\t.reg .pred p;\n\t"                                         \
        "mbarrier.try_wait.parity.acquire.cta.shared::cta.b64 p, [%1], %2;\n\t"   \
        "selp.b32 %0, 1, 0, p;\n\t}"                                              \
        : "=r"(_done) : "r"(_mb), "r"(_ph) : "memory");                           \
    if (!_done) {                                                                 \
        asm volatile("{\n\t.reg .pred P1;\n\t"                                    \
            "WAIT_LOOP_%=:\n\t"                                                   \
            "mbarrier.try_wait.parity.acquire.cta.shared::cta.b64 P1, [%0], %1, 0x989680;\n\t" \
            "@P1 bra.uni WAIT_DONE_%=;\n\t"                                       \
            "bra.uni WAIT_LOOP_%=;\n\t"                                           \
            "WAIT_DONE_%=:\n\t}"                                                  \
            :: "r"(_mb), "r"(_ph) : "memory");                                    \
    }                                                                             \
} while (0)

#define TMA_LOAD_2D(smem_addr, map_ptr, cx, cy, mbar) \
    asm volatile("cp.async.bulk.tensor.2d.shared::cta.global.tile.mbarrier::complete_tx::bytes " \
                 "[%0], [%1, {%2, %3}], [%4];" \
                 :: "r"((uint32_t)(smem_addr)), "l"(map_ptr), \
                    "r"((int32_t)(cx)), "r"((int32_t)(cy)), "r"((uint32_t)(mbar)) : "memory")

// Q pre-scale: D^-0.5 * log2(e)
#define QSCALE 0.18033688011112042f

// ---------------------------------------------------------------------------
// Prep: fused f32 -> fp16 conversion of all three operand tensors (1 launch)
// ---------------------------------------------------------------------------
#define X_N4    (MROWS * EE / 4)
#define WQKV_N4 (3 * EE * EE / 4)
#define WOUT_N4 (EE * EE / 4)
#define PREP_N4 (X_N4 + WQKV_N4 + WOUT_N4)

__global__ void conv_all(const float4* __restrict__ x,
                         const float4* __restrict__ wqkv,
                         const float4* __restrict__ wout)
{
    int i = blockIdx.x * blockDim.x + threadIdx.x;
    if (i >= PREP_N4) return;
    const float4* src;
    uint2* dst;
    if (i < X_N4) {
        src = x + i;
        dst = (uint2*)g_xh + i;
    } else if (i < X_N4 + WQKV_N4) {
        src = wqkv + (i - X_N4);
        dst = (uint2*)g_wqkvh + (i - X_N4);
    } else {
        src = wout + (i - X_N4 - WQKV_N4);
        dst = (uint2*)g_wouth + (i - X_N4 - WQKV_N4);
    }
    float4 v = *src;
    *dst = make_uint2(f2h2(v.x, v.y), f2h2(v.z, v.w));
}

// ---------------------------------------------------------------------------
// fp16 GEMM (NT): CTA 128x128, BK=64, 16 chunks, 8 warps (2m x 4n),
// warp tile 64x32. 3-stage TMA full/empty pipeline, 2 CTAs/SM.
// Race-free: empty arrive AFTER the final mma of each chunk (R14 fix).
// MODE 0: fp32 row-major store. MODE 1: QKV scatter (q scaled, v transposed).
// ---------------------------------------------------------------------------
#define G_NCH 16
#define G_STAGE_BYTES 32768           // A 128x128B + B 128x128B
#define GEMM_SMEM_BYTES (1024 + 3 * G_STAGE_BYTES)

template <int MODE>
__global__ __launch_bounds__(256, 2)
void gemm_tma(const __grid_constant__ CUtensorMap tmA,
              const __grid_constant__ CUtensorMap tmB,
              float* __restrict__ C)
{
    extern __shared__ char smraw[];
    uint32_t sb = smem_u32(smraw);
    sb = (sb + 1023u) & ~1023u;

    const int tid = threadIdx.x, lane = tid & 31, wid = tid >> 5;
    const int wm = wid & 1, wn = wid >> 1;
    const int g = lane >> 2, t = lane & 3;
    const int m0 = blockIdx.y * 128;
    const int n0 = blockIdx.x * 128;

    const uint32_t mbf = sb;             // full  @ +0,8,16
    const uint32_t mbe = sb + 24;        // empty @ +24,32,40
    const uint32_t st0 = sb + 1024;

    if (tid == 0) {
#pragma unroll
        for (int s = 0; s < 3; ++s) {
            MBARRIER_INIT(mbf + s * 8, 1);
            MBARRIER_INIT(mbe + s * 8, 8);
        }
    }
    __syncthreads();

    auto produce = [&](int c) {
        const int s = c % 3;
        MBARRIER_EXPECT_TX(mbf + s * 8, G_STAGE_BYTES);
        const uint32_t sa = st0 + s * G_STAGE_BYTES;
        TMA_LOAD_2D(sa,         &tmA, c * 64, m0, mbf + s * 8);
        TMA_LOAD_2D(sa + 16384, &tmB, c * 64, n0, mbf + s * 8);
    };

    if (tid == 0) { produce(0); produce(1); produce(2); }

    float acc[4][4][4];
#pragma unroll
    for (int mt = 0; mt < 4; ++mt)
#pragma unroll
        for (int nt = 0; nt < 4; ++nt)
#pragma unroll
            for (int j = 0; j < 4; ++j) acc[mt][nt][j] = 0.f;

    for (int c = 0; c < G_NCH; ++c) {
        MBARRIER_WAIT_PARITY(mbf + (c % 3) * 8, (c / 3) & 1);

        const uint32_t sa = st0 + (c % 3) * G_STAGE_BYTES;
        const uint32_t sw = sa + 16384;

        uint32_t af[2][4][4], bf[2][4][2];
        auto ldfrag = [&](int ks, int p) {
            const int kc2 = ks * 2;
#pragma unroll
            for (int mt = 0; mt < 4; ++mt) {
                const int r = wm * 64 + mt * 16 + (lane & 7) + ((lane >> 3) & 1) * 8;
                const int cc = kc2 + (lane >> 4);
                ldsm_x4(af[p][mt][0], af[p][mt][1], af[p][mt][2], af[p][mt][3],
                        sa + r * 128 + ((cc ^ (r & 7)) << 4));
            }
#pragma unroll
            for (int j = 0; j < 2; ++j) {
                const int r = wn * 32 + (j * 2 + ((lane >> 4) & 1)) * 8 + (lane & 7);
                const int cc = kc2 + ((lane >> 3) & 1);
                uint32_t d0, d1, d2, d3;
                ldsm_x4(d0, d1, d2, d3, sw + r * 128 + ((cc ^ (r & 7)) << 4));
                bf[p][2 * j][0] = d0; bf[p][2 * j][1] = d1;
                bf[p][2 * j + 1][0] = d2; bf[p][2 * j + 1][1] = d3;
            }
        };

        ldfrag(0, 0);
#pragma unroll
        for (int ks = 0; ks < 4; ++ks) {
            if (ks < 3) ldfrag(ks + 1, (ks + 1) & 1);
            const int p = ks & 1;
#pragma unroll
            for (int mt = 0; mt < 4; ++mt)
#pragma unroll
                for (int nt = 0; nt < 4; ++nt)
                    mma_f16(acc[mt][nt], af[p][mt][0], af[p][mt][1], af[p][mt][2], af[p][mt][3],
                            bf[p][nt][0], bf[p][nt][1]);
        }

        // RACE FIX: arrive only after ALL mma of this chunk have issued.
        if (lane == 0) MBARRIER_ARRIVE(mbe + (c % 3) * 8);

        if (tid == 0 && c + 3 < G_NCH) {
            MBARRIER_WAIT_PARITY(mbe + (c % 3) * 8, (c / 3) & 1);
            produce(c + 3);
        }
    }

    // Epilogue
#pragma unroll
    for (int mt = 0; mt < 4; ++mt) {
#pragma unroll
        for (int nt = 0; nt < 4; ++nt) {
            const int r0 = m0 + wm * 64 + mt * 16 + g;
            const int col = n0 + wn * 32 + nt * 8 + 2 * t;
            if (MODE == 0) {
                *(float2*)(C + (size_t)r0 * EE + col) =
                    make_float2(acc[mt][nt][0], acc[mt][nt][1]);
                *(float2*)(C + (size_t)(r0 + 8) * EE + col) =
                    make_float2(acc[mt][nt][2], acc[mt][nt][3]);
            } else {
                const int which = col >> 10;
                const int rem = col & 1023;
                const int h = rem >> 6;
                const int d = rem & 63;
#pragma unroll
                for (int half = 0; half < 2; ++half) {
                    const int row = r0 + half * 8;
                    const float v0 = acc[mt][nt][2 * half];
                    const float v1 = acc[mt][nt][2 * half + 1];
                    const int bh = (row >> 11) * HH + h;
                    const int tt = row & 2047;
                    if (which == 0) {
                        *(uint32_t*)(g_qh + ((size_t)bh * TT + tt) * DD + d) =
                            f2h2(v0 * QSCALE, v1 * QSCALE);
                    } else if (which == 1) {
                        *(uint32_t*)(g_kh + ((size_t)bh * TT + tt) * DD + d) =
                            f2h2(v0, v1);
                    } else {
                        g_vth[((size_t)bh * DD + d) * TT + tt]     = __float2half(v0);
                        g_vth[((size_t)bh * DD + d + 1) * TT + tt] = __float2half(v1);
                    }
                }
            }
        }
    }
}

// ---------------------------------------------------------------------------
// Causal flash attention — validated configuration (6.508952e-4):
// q-tile 128, kv-tile 64, 8 warps x 16 q-rows, 2 CTAs/SM, SMEM-P roundtrip,
// Q fragments hoisted, 3-stage kv TMA pipeline, log2-domain softmax.
// ---------------------------------------------------------------------------
#define FA_Q_OFF   1024
#define FA_P_OFF   (FA_Q_OFF + 16384)
#define FA_KV_OFF  (FA_P_OFF + 16384)
#define FA_SMEM_BYTES (FA_KV_OFF + 3 * 16384 + 1024)

__global__ __launch_bounds__(256, 2)
void flash_attn_tma(const __grid_constant__ CUtensorMap tmQ,
                    const __grid_constant__ CUtensorMap tmK,
                    const __grid_constant__ CUtensorMap tmVT)
{
    extern __shared__ char smraw[];
    uint32_t sb = smem_u32(smraw);
    sb = (sb + 1023u) & ~1023u;

    const int qt = gridDim.x - 1 - blockIdx.x;   // long tiles first
    const int bh = blockIdx.y;
    const int q0 = qt * 128;

    const int tid = threadIdx.x, lane = tid & 31, wid = tid >> 5;
    const int g = lane >> 2, t = lane & 3;
    const int wrow = wid * 16;

    const uint32_t qb  = sb + FA_Q_OFF;
    const uint32_t pb  = sb + FA_P_OFF;
    const uint32_t kvb = sb + FA_KV_OFF;
    const uint32_t mbf = sb + 8;    // kv full @ 8,16,24
    const uint32_t mbe = sb + 32;   // kv empty @ 32,40,48

    if (tid == 0) {
        MBARRIER_INIT(sb + 0, 1);
#pragma unroll
        for (int s = 0; s < 3; ++s) {
            MBARRIER_INIT(mbf + s * 8, 1);
            MBARRIER_INIT(mbe + s * 8, 8);
        }
    }
    __syncthreads();

    auto produce_kv = [&](int kt) {
        const int s = kt % 3;
        const int k0 = kt * 64;
        MBARRIER_EXPECT_TX(mbf + s * 8, 16384);
        TMA_LOAD_2D(kvb + s * 16384,        &tmK,  0,  bh * TT + k0, mbf + s * 8);
        TMA_LOAD_2D(kvb + s * 16384 + 8192, &tmVT, k0, bh * 64,      mbf + s * 8);
    };

    const int ktmax = 2 * qt + 1;
    if (tid == 0) {
        MBARRIER_EXPECT_TX(sb + 0, 16384);
        TMA_LOAD_2D(qb, &tmQ, 0, bh * TT + q0, sb + 0);
        produce_kv(0);
        produce_kv(1);
        produce_kv(2);
    }
    MBARRIER_WAIT_PARITY(sb + 0, 0);

    // Hoist Q fragments (constant across kv tiles)
    uint32_t qa[4][4];
#pragma unroll
    for (int ks = 0; ks < 4; ++ks) {
        const int r = wrow + (lane & 7) + ((lane >> 3) & 1) * 8;
        const int cc = ks * 2 + (lane >> 4);
        ldsm_x4(qa[ks][0], qa[ks][1], qa[ks][2], qa[ks][3],
                qb + r * 128 + ((cc ^ (r & 7)) << 4));
    }

    float o[8][4];
#pragma unroll
    for (int nt = 0; nt < 8; ++nt)
#pragma unroll
        for (int j = 0; j < 4; ++j) o[nt][j] = 0.f;
    float mr0 = -INFINITY, mr1 = -INFINITY, lr0 = 0.f, lr1 = 0.f;

    for (int kt = 0; kt <= ktmax; ++kt) {
        const int s3 = kt % 3;
        const int ph = (kt / 3) & 1;
        MBARRIER_WAIT_PARITY(mbf + s3 * 8, ph);

        const int k0 = kt * 64;
        const bool active = (k0 <= q0 + wrow + 15);

        if (active) {
            const uint32_t ks_b = kvb + s3 * 16384;
            const uint32_t vt_b = ks_b + 8192;

            // --- S = Q K^T (Q from registers) ---
            float s[8][4];
#pragma unroll
            for (int nt = 0; nt < 8; ++nt)
#pragma unroll
                for (int j = 0; j < 4; ++j) s[nt][j] = 0.f;

#pragma unroll
            for (int ks = 0; ks < 4; ++ks) {
                const int kc2 = ks * 2;
                uint32_t b[8][2];
#pragma unroll
                for (int j = 0; j < 4; ++j) {
                    const int r = (j * 2 + ((lane >> 4) & 1)) * 8 + (lane & 7);
                    const int cc = kc2 + ((lane >> 3) & 1);
                    uint32_t d0, d1, d2, d3;
                    ldsm_x4(d0, d1, d2, d3, ks_b + r * 128 + ((cc ^ (r & 7)) << 4));
                    b[2 * j][0] = d0; b[2 * j][1] = d1;
                    b[2 * j + 1][0] = d2; b[2 * j + 1][1] = d3;
                }
#pragma unroll
                for (int nt = 0; nt < 8; ++nt)
                    mma_f16(s[nt], qa[ks][0], qa[ks][1], qa[ks][2], qa[ks][3],
                            b[nt][0], b[nt][1]);
            }

            // --- causal mask (diagonal region only) ---
            if (k0 + 63 > q0 + wrow) {
                const int rlo = q0 + wrow + g;
#pragma unroll
                for (int nt = 0; nt < 8; ++nt) {
                    const int key = k0 + nt * 8 + 2 * t;
                    if (key > rlo)         s[nt][0] = -INFINITY;
                    if (key + 1 > rlo)     s[nt][1] = -INFINITY;
                    if (key > rlo + 8)     s[nt][2] = -INFINITY;
                    if (key + 1 > rlo + 8) s[nt][3] = -INFINITY;
                }
            }

            // --- online softmax (log2 domain) + P store (fp16, swizzled) ---
            float mx0 = -INFINITY, mx1 = -INFINITY;
#pragma unroll
            for (int nt = 0; nt < 8; ++nt) {
                mx0 = fmaxf(mx0, fmaxf(s[nt][0], s[nt][1]));
                mx1 = fmaxf(mx1, fmaxf(s[nt][2], s[nt][3]));
            }
            mx0 = fmaxf(mx0, __shfl_xor_sync(0xffffffffu, mx0, 1));
            mx0 = fmaxf(mx0, __shfl_xor_sync(0xffffffffu, mx0, 2));
            mx1 = fmaxf(mx1, __shfl_xor_sync(0xffffffffu, mx1, 1));
            mx1 = fmaxf(mx1, __shfl_xor_sync(0xffffffffu, mx1, 2));

            const float mn0 = fmaxf(mr0, mx0);
            const float mn1 = fmaxf(mr1, mx1);
            const float al0 = ex2f(mr0 - mn0);
            const float al1 = ex2f(mr1 - mn1);
            mr0 = mn0; mr1 = mn1;

            float s0 = 0.f, s1 = 0.f;
#pragma unroll
            for (int nt = 0; nt < 8; ++nt) {
                s[nt][0] = ex2f(s[nt][0] - mn0);
                s[nt][1] = ex2f(s[nt][1] - mn0);
                s[nt][2] = ex2f(s[nt][2] - mn1);
                s[nt][3] = ex2f(s[nt][3] - mn1);
                s0 += s[nt][0] + s[nt][1];
                s1 += s[nt][2] + s[nt][3];
            }
            s0 += __shfl_xor_sync(0xffffffffu, s0, 1);
            s0 += __shfl_xor_sync(0xffffffffu, s0, 2);
            s1 += __shfl_xor_sync(0xffffffffu, s1, 1);
            s1 += __shfl_xor_sync(0xffffffffu, s1, 2);

            lr0 = lr0 * al0 + s0;
            lr1 = lr1 * al1 + s1;
#pragma unroll
            for (int nt = 0; nt < 8; ++nt) {
                o[nt][0] *= al0; o[nt][1] *= al0;
                o[nt][2] *= al1; o[nt][3] *= al1;
            }

#pragma unroll
            for (int half = 0; half < 2; ++half) {
                const int pr = wrow + g + half * 8;
#pragma unroll
                for (int nt = 0; nt < 8; ++nt) {
                    const uint32_t addr = pb + pr * 128 +
                                          ((nt ^ (pr & 7)) << 4) + 4 * t;
                    const uint32_t val = f2h2(s[nt][2 * half], s[nt][2 * half + 1]);
                    asm volatile("st.shared.b32 [%0], %1;"
                                 :: "r"(addr), "r"(val) : "memory");
                }
            }
            __syncwarp();

            // --- O += P V (P from SMEM, proven path) ---
#pragma unroll
            for (int ks = 0; ks < 4; ++ks) {
                const int kc2 = ks * 2;
                uint32_t a[4];
                {
                    const int r = wrow + (lane & 7) + ((lane >> 3) & 1) * 8;
                    const int cc = kc2 + (lane >> 4);
                    ldsm_x4(a[0], a[1], a[2], a[3],
                            pb + r * 128 + ((cc ^ (r & 7)) << 4));
                }
                uint32_t b[8][2];
#pragma unroll
                for (int j = 0; j < 4; ++j) {
                    const int r = (j * 2 + ((lane >> 4) & 1)) * 8 + (lane & 7);
                    const int cc = kc2 + ((lane >> 3) & 1);
                    uint32_t d0, d1, d2, d3;
                    ldsm_x4(d0, d1, d2, d3, vt_b + r * 128 + ((cc ^ (r & 7)) << 4));
                    b[2 * j][0] = d0; b[2 * j][1] = d1;
                    b[2 * j + 1][0] = d2; b[2 * j + 1][1] = d3;
                }
#pragma unroll
                for (int nt = 0; nt < 8; ++nt)
                    mma_f16(o[nt], a[0], a[1], a[2], a[3], b[nt][0], b[nt][1]);
            }
        }

        if (lane == 0) MBARRIER_ARRIVE(mbe + s3 * 8);

        if (tid == 0 && kt + 3 <= ktmax) {
            MBARRIER_WAIT_PARITY(mbe + s3 * 8, ph);
            produce_kv(kt + 3);
        }
    }

    // --- epilogue: normalize, write fp16 att [B,T,E] ---
    const int b = bh >> 4, h = bh & 15;
#pragma unroll
    for (int half = 0; half < 2; ++half) {
        const int row = q0 + wrow + g + half * 8;
        const float inv = 1.0f / (half ? lr1 : lr0);
#pragma unroll
        for (int nt = 0; nt < 8; ++nt) {
            const int col = h * 64 + nt * 8 + 2 * t;
            *(uint32_t*)(g_atth + ((size_t)b * TT + row) * EE + col) =
                f2h2(o[nt][2 * half] * inv, o[nt][2 * half + 1] * inv);
        }
    }
}

// ---------------------------------------------------------------------------
// Host
// ---------------------------------------------------------------------------
typedef CUresult (*EncodeFn)(CUtensorMap*, CUtensorMapDataType, cuuint32_t, void*,
                             const cuuint64_t*, const cuuint64_t*, const cuuint32_t*,
                             const cuuint32_t*, CUtensorMapInterleave, CUtensorMapSwizzle,
                             CUtensorMapL2promotion, CUtensorMapFloatOOBfill);

static void make_tm(EncodeFn enc, CUtensorMap* tm, void* ptr,
                    uint64_t d0, uint64_t d1, uint32_t b0, uint32_t b1)
{
    cuuint64_t dims[2]    = {d0, d1};
    cuuint64_t strides[1] = {d0 * 2};
    cuuint32_t box[2]     = {b0, b1};
    cuuint32_t estr[2]    = {1, 1};
    enc(tm, CU_TENSOR_MAP_DATA_TYPE_FLOAT16, 2, ptr, dims, strides, box, estr,
        CU_TENSOR_MAP_INTERLEAVE_NONE, CU_TENSOR_MAP_SWIZZLE_128B,
        CU_TENSOR_MAP_L2_PROMOTION_L2_128B, CU_TENSOR_MAP_FLOAT_OOB_FILL_NONE);
}

extern "C" void kernel_launch(void* const* d_in, const int* in_sizes, int n_in,
                              void* d_out, int out_size)
{
    const float* x    = (const float*)d_in[0];   // [B,T,E]
    const float* Wqkv = (const float*)d_in[1];   // [3E,E]
    const float* Wout = (const float*)d_in[2];   // [E,E]
    float* out = (float*)d_out;                  // [B,T,E]

    void *xh, *wqkvh, *wouth, *atth, *qp, *kp, *vtp;
    cudaGetSymbolAddress(&xh, g_xh);
    cudaGetSymbolAddress(&wqkvh, g_wqkvh);
    cudaGetSymbolAddress(&wouth, g_wouth);
    cudaGetSymbolAddress(&atth, g_atth);
    cudaGetSymbolAddress(&qp, g_qh);
    cudaGetSymbolAddress(&kp, g_kh);
    cudaGetSymbolAddress(&vtp, g_vth);

    void* pf = nullptr;
    cudaDriverEntryPointQueryResult qr;
    cudaGetDriverEntryPoint("cuTensorMapEncodeTiled", &pf, cudaEnableDefault, &qr);
    EncodeFn enc = (EncodeFn)pf;

    CUtensorMap tmX, tmWqkv, tmAtt, tmWout, tmQ, tmK, tmVT;
    make_tm(enc, &tmX,    xh,    1024, MROWS,               64, 128);
    make_tm(enc, &tmWqkv, wqkvh, 1024, 3072,                64, 128);
    make_tm(enc, &tmAtt,  atth,  1024, MROWS,               64, 128);
    make_tm(enc, &tmWout, wouth, 1024, 1024,                64, 128);
    make_tm(enc, &tmQ,    qp,    64,   (uint64_t)BB * HH * TT, 64, 128);
    make_tm(enc, &tmK,    kp,    64,   (uint64_t)BB * HH * TT, 64, 64);
    make_tm(enc, &tmVT,   vtp,   2048, (uint64_t)BB * HH * DD, 64, 64);

    cudaFuncSetAttribute(gemm_tma<0>, cudaFuncAttributeMaxDynamicSharedMemorySize, GEMM_SMEM_BYTES);
    cudaFuncSetAttribute(gemm_tma<1>, cudaFuncAttributeMaxDynamicSharedMemorySize, GEMM_SMEM_BYTES);
    cudaFuncSetAttribute(flash_attn_tma, cudaFuncAttributeMaxDynamicSharedMemorySize, FA_SMEM_BYTES);

    // 0) convert all operands to fp16 in one launch
    conv_all<<<(PREP_N4 + 255) / 256, 256>>>((const float4*)x, (const float4*)Wqkv,
                                             (const float4*)Wout);

    // 1) QKV projection + scatter (q scaled, v transposed)
    {
        dim3 grid(3 * EE / 128, MROWS / 128);   // (24, 64)
        gemm_tma<1><<<grid, 256, GEMM_SMEM_BYTES>>>(tmX, tmWqkv, nullptr);
    }

    // 2) Causal flash attention -> g_atth (fp16)
    {
        dim3 grid(TT / 128, BB * HH);           // (16, 64)
        flash_attn_tma<<<grid, 256, FA_SMEM_BYTES>>>(tmQ, tmK, tmVT);
    }

    // 3) Output projection (fp32 out)
    {
        dim3 grid(EE / 128, MROWS / 128);       // (8, 64)
        gemm_tma<0><<<grid, 256, GEMM_SMEM_BYTES>>>(tmAtt, tmWout, out);
    }
}